// round 1
// baseline (speedup 1.0000x reference)
#include <cuda_runtime.h>
#include <math.h>

namespace {

constexpr int   NN    = 12;
constexpr int   HID   = 64;
constexpr float SLOPE = 0.2f;
constexpr float ALPHA = 0.1f;
constexpr int   NTH   = 512;   // 2 sub-blocks of 256
constexpr int   GRID  = 1024;  // 4 graphs per block -> 4096

// output section offsets (fp32 elements)
constexpr size_t O1 = 0;        // batch[:,:,:4]   4096*12*4
constexpr size_t O2 = 196608;   // batch[:,:,4:5]  4096*12*1
constexpr size_t OL = 245760;   // logits          4096*12*4
constexpr size_t OV = 442368;   // values          4096*12*1
constexpr size_t OT = 491520;   // latent          4096*12*3

struct alignas(16) SubS {
    float binp[64];          // 12*5 input, padded
    float xbuf[NN * HID];    // h1, then x3/x4
    float xcur[NN * HID];    // h2, then x1
    float x2s [NN * HID];    // x2 (kept for gat3+gat4)
    float xl  [NN * HID];
    float xr  [NN * HID];
    float skipb[NN * HID];
    float latent[NN * 4];    // padded stride 4
    float e   [NN * NN];     // scores -> probs
    int   gab [NN * NN];
    int   adj [NN * NN];
};

struct alignas(16) SM {
    float w_enc1[5 * HID],  b_enc1[HID];
    float w_enc2[HID * HID], b_enc2[HID];
    float w_enc3[HID * 3],  b_enc3[4];
    float g_wl1[HID], g_wr1[HID];
    float g_wl2[HID * HID], g_wr2[HID * HID];
    float g_wl3[HID * HID], g_wr3[HID * HID];
    float g_wl4[HID * HID], g_wr4[HID * HID];
    float att1[HID], att2[HID], att3[HID], att4[HID];
    float gb1[HID],  gb2[HID],  gb3[HID],  gb4[HID];
    float w_skip[3 * HID], b_skip[HID];
    float w_lab[HID * 4],  b_lab[4];
    float w_val[HID],      b_val[4];
    SubS  sub[2];
};

// Y[n,h] = relu(bias[h] + sum_k X[n,k] * W[k,h]) for 3 rows per thread
__device__ __forceinline__ void gemm64_relu(const float* __restrict__ X,
                                            const float* __restrict__ W,
                                            const float* __restrict__ bias,
                                            float* __restrict__ Y, int h, int g)
{
    const int n0 = g, n1 = g + 4, n2 = g + 8;
    float a0 = bias[h], a1 = a0, a2 = a0;
    const float4* X0 = (const float4*)(X + n0 * HID);
    const float4* X1 = (const float4*)(X + n1 * HID);
    const float4* X2 = (const float4*)(X + n2 * HID);
#pragma unroll
    for (int k4 = 0; k4 < 16; ++k4) {
        float4 x0 = X0[k4], x1 = X1[k4], x2 = X2[k4];
        const float* Wp = W + (k4 * 4) * HID + h;
        float w0 = Wp[0], w1 = Wp[HID], w2 = Wp[2 * HID], w3 = Wp[3 * HID];
        a0 = fmaf(x0.x, w0, a0); a0 = fmaf(x0.y, w1, a0); a0 = fmaf(x0.z, w2, a0); a0 = fmaf(x0.w, w3, a0);
        a1 = fmaf(x1.x, w0, a1); a1 = fmaf(x1.y, w1, a1); a1 = fmaf(x1.z, w2, a1); a1 = fmaf(x1.w, w3, a1);
        a2 = fmaf(x2.x, w0, a2); a2 = fmaf(x2.y, w1, a2); a2 = fmaf(x2.z, w2, a2); a2 = fmaf(x2.w, w3, a2);
    }
    Y[n0 * HID + h] = fmaxf(a0, 0.f);
    Y[n1 * HID + h] = fmaxf(a1, 0.f);
    Y[n2 * HID + h] = fmaxf(a2, 0.f);
}

// xl = X @ WL, xr = X @ WR (no bias/relu), 3 rows per thread
__device__ __forceinline__ void dual_gemm64(const float* __restrict__ X,
                                            const float* __restrict__ WL,
                                            const float* __restrict__ WR,
                                            float* __restrict__ XL,
                                            float* __restrict__ XR, int h, int g)
{
    const int n0 = g, n1 = g + 4, n2 = g + 8;
    float l0 = 0.f, l1 = 0.f, l2 = 0.f;
    float r0 = 0.f, r1 = 0.f, r2 = 0.f;
    const float4* X0 = (const float4*)(X + n0 * HID);
    const float4* X1 = (const float4*)(X + n1 * HID);
    const float4* X2 = (const float4*)(X + n2 * HID);
#pragma unroll
    for (int k4 = 0; k4 < 16; ++k4) {
        float4 x0 = X0[k4], x1 = X1[k4], x2 = X2[k4];
        const float* Lp = WL + (k4 * 4) * HID + h;
        const float* Rp = WR + (k4 * 4) * HID + h;
        float wl0 = Lp[0], wl1 = Lp[HID], wl2 = Lp[2 * HID], wl3 = Lp[3 * HID];
        float wr0 = Rp[0], wr1 = Rp[HID], wr2 = Rp[2 * HID], wr3 = Rp[3 * HID];
        l0 = fmaf(x0.x, wl0, l0); l0 = fmaf(x0.y, wl1, l0); l0 = fmaf(x0.z, wl2, l0); l0 = fmaf(x0.w, wl3, l0);
        l1 = fmaf(x1.x, wl0, l1); l1 = fmaf(x1.y, wl1, l1); l1 = fmaf(x1.z, wl2, l1); l1 = fmaf(x1.w, wl3, l1);
        l2 = fmaf(x2.x, wl0, l2); l2 = fmaf(x2.y, wl1, l2); l2 = fmaf(x2.z, wl2, l2); l2 = fmaf(x2.w, wl3, l2);
        r0 = fmaf(x0.x, wr0, r0); r0 = fmaf(x0.y, wr1, r0); r0 = fmaf(x0.z, wr2, r0); r0 = fmaf(x0.w, wr3, r0);
        r1 = fmaf(x1.x, wr0, r1); r1 = fmaf(x1.y, wr1, r1); r1 = fmaf(x1.z, wr2, r1); r1 = fmaf(x1.w, wr3, r1);
        r2 = fmaf(x2.x, wr0, r2); r2 = fmaf(x2.y, wr1, r2); r2 = fmaf(x2.z, wr2, r2); r2 = fmaf(x2.w, wr3, r2);
    }
    XL[n0 * HID + h] = l0; XL[n1 * HID + h] = l1; XL[n2 * HID + h] = l2;
    XR[n0 * HID + h] = r0; XR[n1 * HID + h] = r1; XR[n2 * HID + h] = r2;
}

// attention scores + softmax; contains 3 barriers, called by ALL threads
__device__ __forceinline__ void gat_attn(SubS& s, const float* __restrict__ attv, int tid)
{
    if (tid < NN * NN) {
        const int i = tid / NN, j = tid % NN;
        float acc = -1000000000.0f;
        if (s.adj[tid]) {
            float a0 = 0.f, a1 = 0.f;
            const float* xlj = s.xl + j * HID;
            const float* xri = s.xr + i * HID;
#pragma unroll
            for (int t = 0; t < 64; t += 2) {
                int h0 = (t + tid) & 63;
                int h1 = (t + 1 + tid) & 63;
                float v0 = xlj[h0] + xri[h0];
                float v1 = xlj[h1] + xri[h1];
                v0 = fmaxf(v0, SLOPE * v0);
                v1 = fmaxf(v1, SLOPE * v1);
                a0 = fmaf(v0, attv[h0], a0);
                a1 = fmaf(v1, attv[h1], a1);
            }
            acc = a0 + a1;
        }
        s.e[tid] = acc;
    }
    __syncthreads();
    if (tid < NN) {
        const int i = tid;
        float m = -3.4e38f;
#pragma unroll
        for (int j = 0; j < NN; ++j) m = fmaxf(m, s.e[i * NN + j]);
        float vals[NN];
        float ssum = 0.f;
#pragma unroll
        for (int j = 0; j < NN; ++j) {
            float v = expf(s.e[i * NN + j] - m);
            vals[j] = v;
            ssum += v;
        }
#pragma unroll
        for (int j = 0; j < NN; ++j) s.e[i * NN + j] = vals[j] / ssum;
    }
    __syncthreads();
}

// out[n,h] = sum_j a[n,j]*xl[j,h] + bias[h], then relu (mode 0) or relu(+alpha*skip) (mode 1)
__device__ __forceinline__ void gat_agg(SubS& s, const float* __restrict__ bias,
                                        float* __restrict__ xout, int h, int g, int mode)
{
    const int n0 = g, n1 = g + 4, n2 = g + 8;
    float a0 = bias[h], a1 = a0, a2 = a0;
#pragma unroll
    for (int j = 0; j < NN; ++j) {
        float xv = s.xl[j * HID + h];
        a0 = fmaf(s.e[n0 * NN + j], xv, a0);
        a1 = fmaf(s.e[n1 * NN + j], xv, a1);
        a2 = fmaf(s.e[n2 * NN + j], xv, a2);
    }
    if (mode == 1) {
        a0 += ALPHA * s.skipb[n0 * HID + h];
        a1 += ALPHA * s.skipb[n1 * HID + h];
        a2 += ALPHA * s.skipb[n2 * HID + h];
    }
    xout[n0 * HID + h] = fmaxf(a0, 0.f);
    xout[n1 * HID + h] = fmaxf(a1, 0.f);
    xout[n2 * HID + h] = fmaxf(a2, 0.f);
}

__global__ void __launch_bounds__(NTH, 1)
gae_kernel(const float* __restrict__ batch,
           const float* __restrict__ enc_w1, const float* __restrict__ enc_b1,
           const float* __restrict__ enc_w2, const float* __restrict__ enc_b2,
           const float* __restrict__ enc_w3, const float* __restrict__ enc_b3,
           const float* __restrict__ g1_wl, const float* __restrict__ g1_wr,
           const float* __restrict__ g1_att, const float* __restrict__ g1_b,
           const float* __restrict__ g2_wl, const float* __restrict__ g2_wr,
           const float* __restrict__ g2_att, const float* __restrict__ g2_b,
           const float* __restrict__ g3_wl, const float* __restrict__ g3_wr,
           const float* __restrict__ g3_att, const float* __restrict__ g3_b,
           const float* __restrict__ g4_wl, const float* __restrict__ g4_wr,
           const float* __restrict__ g4_att, const float* __restrict__ g4_b,
           const float* __restrict__ lab_w, const float* __restrict__ lab_b,
           const float* __restrict__ val_w, const float* __restrict__ val_b,
           const float* __restrict__ skip_w, const float* __restrict__ skip_b,
           float* __restrict__ out)
{
    extern __shared__ unsigned char smraw[];
    SM& S = *reinterpret_cast<SM*>(smraw);
    const int T = threadIdx.x;

    // ---- stage all weights into shared (once per block) ----
    for (int i = T; i < 5 * HID; i += NTH) S.w_enc1[i] = enc_w1[i];
    for (int i = T; i < HID * HID; i += NTH) {
        S.w_enc2[i] = enc_w2[i];
        S.g_wl2[i] = g2_wl[i]; S.g_wr2[i] = g2_wr[i];
        S.g_wl3[i] = g3_wl[i]; S.g_wr3[i] = g3_wr[i];
        S.g_wl4[i] = g4_wl[i]; S.g_wr4[i] = g4_wr[i];
    }
    for (int i = T; i < HID; i += NTH) {
        S.b_enc1[i] = enc_b1[i]; S.b_enc2[i] = enc_b2[i];
        S.g_wl1[i] = g1_wl[i];   S.g_wr1[i] = g1_wr[i];
        S.att1[i] = g1_att[i];   S.gb1[i] = g1_b[i];
        S.att2[i] = g2_att[i];   S.gb2[i] = g2_b[i];
        S.att3[i] = g3_att[i];   S.gb3[i] = g3_b[i];
        S.att4[i] = g4_att[i];   S.gb4[i] = g4_b[i];
        S.b_skip[i] = skip_b[i]; S.w_val[i] = val_w[i];
    }
    for (int i = T; i < 3 * HID; i += NTH) { S.w_enc3[i] = enc_w3[i]; S.w_skip[i] = skip_w[i]; }
    for (int i = T; i < HID * 4; i += NTH) S.w_lab[i] = lab_w[i];
    if (T < 3) S.b_enc3[T] = enc_b3[T];
    if (T < 4) S.b_lab[T] = lab_b[T];
    if (T == 0) S.b_val[0] = val_b[0];
    __syncthreads();

    const int sb  = T >> 8;        // which sub-block (graph slot)
    const int tid = T & 255;
    SubS& s = S.sub[sb];
    const int h = tid & 63;
    const int g = tid >> 6;        // 0..3
    const int n0 = g, n1 = g + 4, n2 = g + 8;

    for (int it = 0; it < 2; ++it) {
        const int b = blockIdx.x * 4 + it * 2 + sb;

        // ---- phase 0: load input, emit passthrough outputs ----
        if (tid < 60) {
            float v = batch[(size_t)b * 60 + tid];
            s.binp[tid] = v;
            int n = tid / 5, c = tid % 5;
            if (c < 4) out[O1 + (size_t)b * 48 + n * 4 + c] = v;
            else       out[O2 + (size_t)b * 12 + n] = v;
        }
        __syncthreads();

        // ---- encoder layer 1 (K=5) -> xbuf ----
        {
            float a0 = S.b_enc1[h], a1 = a0, a2 = a0;
#pragma unroll
            for (int k = 0; k < 5; ++k) {
                float w = S.w_enc1[k * HID + h];
                a0 = fmaf(s.binp[n0 * 5 + k], w, a0);
                a1 = fmaf(s.binp[n1 * 5 + k], w, a1);
                a2 = fmaf(s.binp[n2 * 5 + k], w, a2);
            }
            s.xbuf[n0 * HID + h] = fmaxf(a0, 0.f);
            s.xbuf[n1 * HID + h] = fmaxf(a1, 0.f);
            s.xbuf[n2 * HID + h] = fmaxf(a2, 0.f);
        }
        __syncthreads();

        // ---- encoder layer 2 (64x64) -> xcur ----
        gemm64_relu(s.xbuf, S.w_enc2, S.b_enc2, s.xcur, h, g);
        __syncthreads();

        // ---- latent (64 -> 3) + emit ----
        if (tid < 36) {
            int n = tid / 3, c = tid % 3;
            float a = S.b_enc3[c];
#pragma unroll
            for (int k = 0; k < 64; ++k) {
                int kk = (k + tid) & 63;
                a = fmaf(s.xcur[n * HID + kk], S.w_enc3[kk * 3 + c], a);
            }
            s.latent[n * 4 + c] = a;
            out[OT + (size_t)b * 36 + n * 3 + c] = a;
        }
        __syncthreads();

        // ---- Gabriel adjacency ----
        if (tid < NN * NN) {
            int i = tid / NN, j = tid % NN;
            float xi = s.latent[i * 4], yi = s.latent[i * 4 + 1];
            float xj = s.latent[j * 4], yj = s.latent[j * 4 + 1];
            float dx = xi - xj, dy = yi - yj;
            float r2 = (dx * dx + dy * dy) * 0.25f;
            float mx = (xi + xj) * 0.5f, my = (yi + yj) * 0.5f;
            int ok = 1;
#pragma unroll
            for (int k = 0; k < NN; ++k) {
                if (k == i || k == j) continue;
                float ax = s.latent[k * 4] - mx;
                float ay = s.latent[k * 4 + 1] - my;
                float d2 = ax * ax + ay * ay;
                ok &= (d2 > r2) ? 1 : 0;
            }
            s.gab[tid] = (i != j) ? ok : 0;
        }
        __syncthreads();

        // ---- adj = gab | gab^T | eye ; and skip projection ----
        if (tid < NN * NN) {
            int i = tid / NN, j = tid % NN;
            s.adj[tid] = s.gab[i * NN + j] | s.gab[j * NN + i] | (i == j ? 1 : 0);
        }
        {
            float a0 = S.b_skip[h], a1 = a0, a2 = a0;
#pragma unroll
            for (int c = 0; c < 3; ++c) {
                float w = S.w_skip[c * HID + h];
                a0 = fmaf(s.latent[n0 * 4 + c], w, a0);
                a1 = fmaf(s.latent[n1 * 4 + c], w, a1);
                a2 = fmaf(s.latent[n2 * 4 + c], w, a2);
            }
            s.skipb[n0 * HID + h] = a0;
            s.skipb[n1 * HID + h] = a1;
            s.skipb[n2 * HID + h] = a2;
        }
        __syncthreads();

        // ---- GAT 1 (cin = 1, x0 = latent[:,2]) -> xcur ----
        {
            float wl = S.g_wl1[h], wr = S.g_wr1[h];
            float v0 = s.latent[n0 * 4 + 2], v1 = s.latent[n1 * 4 + 2], v2 = s.latent[n2 * 4 + 2];
            s.xl[n0 * HID + h] = v0 * wl; s.xr[n0 * HID + h] = v0 * wr;
            s.xl[n1 * HID + h] = v1 * wl; s.xr[n1 * HID + h] = v1 * wr;
            s.xl[n2 * HID + h] = v2 * wl; s.xr[n2 * HID + h] = v2 * wr;
        }
        __syncthreads();
        gat_attn(s, S.att1, tid);
        gat_agg(s, S.gb1, s.xcur, h, g, 0);
        __syncthreads();

        // ---- GAT 2 -> x2s ----
        dual_gemm64(s.xcur, S.g_wl2, S.g_wr2, s.xl, s.xr, h, g);
        __syncthreads();
        gat_attn(s, S.att2, tid);
        gat_agg(s, S.gb2, s.x2s, h, g, 0);
        __syncthreads();

        // ---- GAT 3 -> xbuf (x3 = relu(gat + alpha*skip)) ----
        dual_gemm64(s.x2s, S.g_wl3, S.g_wr3, s.xl, s.xr, h, g);
        __syncthreads();
        gat_attn(s, S.att3, tid);
        gat_agg(s, S.gb3, s.xbuf, h, g, 1);
        __syncthreads();

        // ---- logits head (reads xbuf) + GAT4 projections (writes xl/xr) ----
        dual_gemm64(s.x2s, S.g_wl4, S.g_wr4, s.xl, s.xr, h, g);
        if (tid < 48) {
            int n = tid / 4, c = tid % 4;
            float a = S.b_lab[c];
#pragma unroll
            for (int k = 0; k < 64; ++k) {
                int kk = (k + tid) & 63;
                a = fmaf(s.xbuf[n * HID + kk], S.w_lab[kk * 4 + c], a);
            }
            out[OL + (size_t)b * 48 + n * 4 + c] = a;
        }
        __syncthreads();

        // ---- GAT 4 rest -> xbuf (x4) ----
        gat_attn(s, S.att4, tid);
        gat_agg(s, S.gb4, s.xbuf, h, g, 1);
        __syncthreads();

        // ---- values head ----
        if (tid < NN) {
            int n = tid;
            float a = S.b_val[0];
#pragma unroll
            for (int k = 0; k < 64; ++k) {
                int kk = (k + tid) & 63;
                a = fmaf(s.xbuf[n * HID + kk], S.w_val[kk], a);
            }
            out[OV + (size_t)b * 12 + n] = a;
        }
        // next iteration's first barrier (after binp load) orders xbuf reuse
    }
}

} // anonymous namespace

extern "C" void kernel_launch(void* const* d_in, const int* in_sizes, int n_in,
                              void* d_out, int out_size)
{
    const float* p[29];
    for (int i = 0; i < 29; ++i) p[i] = (const float*)d_in[i];
    float* out = (float*)d_out;

    cudaFuncSetAttribute(gae_kernel, cudaFuncAttributeMaxDynamicSharedMemorySize,
                         (int)sizeof(SM));

    gae_kernel<<<GRID, NTH, sizeof(SM)>>>(
        p[0],
        p[1], p[2], p[3], p[4], p[5], p[6],
        p[7], p[8], p[9], p[10],
        p[11], p[12], p[13], p[14],
        p[15], p[16], p[17], p[18],
        p[19], p[20], p[21], p[22],
        p[23], p[24], p[25], p[26], p[27], p[28],
        out);
}

// round 2
// speedup vs baseline: 1.7960x; 1.7960x over previous
#include <cuda_runtime.h>
#include <math.h>

namespace {

constexpr int   NN    = 12;
constexpr int   HID   = 64;
constexpr int   PAD   = 68;    // padded row stride (floats) for conflict-free LDS.128
constexpr float SLOPE = 0.2f;
constexpr float ALPHA = 0.1f;
constexpr int   NTH   = 1024;  // 4 sub-blocks of 256 -> 4 graphs per block
constexpr int   NSUB  = 4;
constexpr int   GRID  = 1024;  // 4096 graphs

// output section offsets (fp32 elements)
constexpr size_t O1 = 0;        // batch[:,:,:4]
constexpr size_t O2 = 196608;   // batch[:,:,4]
constexpr size_t OL = 245760;   // logits
constexpr size_t OV = 442368;   // values
constexpr size_t OT = 491520;   // latent

struct alignas(16) SubS {
    float binp[64];           // 12*5 input
    float xbuf[NN * HID];     // h1, then x3/x4
    float xcur[NN * HID];     // h2, then x1
    float x2s [NN * HID];     // x2 (kept for gat3+gat4)
    float skipb[NN * HID];
    float xl  [NN * PAD];     // padded for vector loads
    float xr  [NN * PAD];
    float latent[NN * 4];
    float e   [NN * NN];
    int   gab [NN * NN];
};

struct alignas(16) SM {
    float w_enc1[5 * HID],   b_enc1[HID];
    float w_enc2t[HID * PAD], b_enc2[HID];    // transposed [h][k], padded
    float w_enc3[HID * 3],   b_enc3[4];
    float g_wl1[HID], g_wr1[HID];
    float wl2t[HID * PAD], wr2t[HID * PAD];
    float wl3t[HID * PAD], wr3t[HID * PAD];
    float wl4t[HID * PAD], wr4t[HID * PAD];
    float att1[HID], att2[HID], att3[HID], att4[HID];
    float gb1[HID],  gb2[HID],  gb3[HID],  gb4[HID];
    float w_skip[3 * HID], b_skip[HID];
    float w_lab[HID * 4],  b_lab[4];
    float w_val[HID],      b_val[4];
    SubS  sub[NSUB];
};

__device__ __forceinline__ void barsub(int sb)
{
    asm volatile("bar.sync %0, 256;" :: "r"(sb + 1) : "memory");
}

// Y[n,h] = relu(bias[h] + sum_k X[n,k] * Wt[h,k]) ; Wt padded transposed
__device__ __forceinline__ void gemm64_relu(const float* __restrict__ X,
                                            const float* __restrict__ Wt,
                                            const float* __restrict__ bias,
                                            float* __restrict__ Y, int h, int g)
{
    const int n0 = g, n1 = g + 4, n2 = g + 8;
    float a0 = bias[h], a1 = a0, a2 = a0;
    const float4* X0 = (const float4*)(X + n0 * HID);
    const float4* X1 = (const float4*)(X + n1 * HID);
    const float4* X2 = (const float4*)(X + n2 * HID);
    const float4* Wp = (const float4*)(Wt + h * PAD);
#pragma unroll
    for (int k4 = 0; k4 < 16; ++k4) {
        float4 w  = Wp[k4];
        float4 x0 = X0[k4], x1 = X1[k4], x2 = X2[k4];
        a0 = fmaf(x0.x, w.x, a0); a0 = fmaf(x0.y, w.y, a0); a0 = fmaf(x0.z, w.z, a0); a0 = fmaf(x0.w, w.w, a0);
        a1 = fmaf(x1.x, w.x, a1); a1 = fmaf(x1.y, w.y, a1); a1 = fmaf(x1.z, w.z, a1); a1 = fmaf(x1.w, w.w, a1);
        a2 = fmaf(x2.x, w.x, a2); a2 = fmaf(x2.y, w.y, a2); a2 = fmaf(x2.z, w.z, a2); a2 = fmaf(x2.w, w.w, a2);
    }
    Y[n0 * HID + h] = fmaxf(a0, 0.f);
    Y[n1 * HID + h] = fmaxf(a1, 0.f);
    Y[n2 * HID + h] = fmaxf(a2, 0.f);
}

// xl = X @ WL, xr = X @ WR (transposed padded weights), outputs stride PAD
__device__ __forceinline__ void dual_gemm64(const float* __restrict__ X,
                                            const float* __restrict__ WLt,
                                            const float* __restrict__ WRt,
                                            float* __restrict__ XL,
                                            float* __restrict__ XR, int h, int g)
{
    const int n0 = g, n1 = g + 4, n2 = g + 8;
    float l0 = 0.f, l1 = 0.f, l2 = 0.f;
    float r0 = 0.f, r1 = 0.f, r2 = 0.f;
    const float4* X0 = (const float4*)(X + n0 * HID);
    const float4* X1 = (const float4*)(X + n1 * HID);
    const float4* X2 = (const float4*)(X + n2 * HID);
    const float4* Lp = (const float4*)(WLt + h * PAD);
    const float4* Rp = (const float4*)(WRt + h * PAD);
#pragma unroll
    for (int k4 = 0; k4 < 16; ++k4) {
        float4 wl = Lp[k4];
        float4 wr = Rp[k4];
        float4 x0 = X0[k4], x1 = X1[k4], x2 = X2[k4];
        l0 = fmaf(x0.x, wl.x, l0); l0 = fmaf(x0.y, wl.y, l0); l0 = fmaf(x0.z, wl.z, l0); l0 = fmaf(x0.w, wl.w, l0);
        l1 = fmaf(x1.x, wl.x, l1); l1 = fmaf(x1.y, wl.y, l1); l1 = fmaf(x1.z, wl.z, l1); l1 = fmaf(x1.w, wl.w, l1);
        l2 = fmaf(x2.x, wl.x, l2); l2 = fmaf(x2.y, wl.y, l2); l2 = fmaf(x2.z, wl.z, l2); l2 = fmaf(x2.w, wl.w, l2);
        r0 = fmaf(x0.x, wr.x, r0); r0 = fmaf(x0.y, wr.y, r0); r0 = fmaf(x0.z, wr.z, r0); r0 = fmaf(x0.w, wr.w, r0);
        r1 = fmaf(x1.x, wr.x, r1); r1 = fmaf(x1.y, wr.y, r1); r1 = fmaf(x1.z, wr.z, r1); r1 = fmaf(x1.w, wr.w, r1);
        r2 = fmaf(x2.x, wr.x, r2); r2 = fmaf(x2.y, wr.y, r2); r2 = fmaf(x2.z, wr.z, r2); r2 = fmaf(x2.w, wr.w, r2);
    }
    XL[n0 * PAD + h] = l0; XL[n1 * PAD + h] = l1; XL[n2 * PAD + h] = l2;
    XR[n0 * PAD + h] = r0; XR[n1 * PAD + h] = r1; XR[n2 * PAD + h] = r2;
}

__device__ __forceinline__ float lrelu(float v) { return fmaxf(v, SLOPE * v); }

// attention scores + softmax; 2 named barriers inside
__device__ __forceinline__ void gat_attn(SubS& s, const float* __restrict__ attv,
                                         int tid, int ai, int aj, int adjv, int sb)
{
    if (tid < NN * NN) {
        float acc = -1000000000.0f;
        if (adjv) {
            float a0 = 0.f, a1 = 0.f;
            const float4* xlj = (const float4*)(s.xl + aj * PAD);
            const float4* xri = (const float4*)(s.xr + ai * PAD);
            const float4* at4 = (const float4*)attv;
#pragma unroll
            for (int k = 0; k < 16; k += 2) {
                float4 l0 = xlj[k],     r0 = xri[k],     w0 = at4[k];
                float4 l1 = xlj[k + 1], r1 = xri[k + 1], w1 = at4[k + 1];
                a0 = fmaf(lrelu(l0.x + r0.x), w0.x, a0);
                a0 = fmaf(lrelu(l0.y + r0.y), w0.y, a0);
                a0 = fmaf(lrelu(l0.z + r0.z), w0.z, a0);
                a0 = fmaf(lrelu(l0.w + r0.w), w0.w, a0);
                a1 = fmaf(lrelu(l1.x + r1.x), w1.x, a1);
                a1 = fmaf(lrelu(l1.y + r1.y), w1.y, a1);
                a1 = fmaf(lrelu(l1.z + r1.z), w1.z, a1);
                a1 = fmaf(lrelu(l1.w + r1.w), w1.w, a1);
            }
            acc = a0 + a1;
        }
        s.e[tid] = acc;
    }
    barsub(sb);
    if (tid < NN) {
        const int i = tid;
        float m = -3.4e38f;
#pragma unroll
        for (int j = 0; j < NN; ++j) m = fmaxf(m, s.e[i * NN + j]);
        float vals[NN];
        float ssum = 0.f;
#pragma unroll
        for (int j = 0; j < NN; ++j) {
            float v = __expf(s.e[i * NN + j] - m);
            vals[j] = v;
            ssum += v;
        }
        float r = 1.0f / ssum;
#pragma unroll
        for (int j = 0; j < NN; ++j) s.e[i * NN + j] = vals[j] * r;
    }
    barsub(sb);
}

// out[n,h] = relu(sum_j a[n,j]*xl[j,h] + bias[h] [+ alpha*skip])
__device__ __forceinline__ void gat_agg(SubS& s, const float* __restrict__ bias,
                                        float* __restrict__ xout, int h, int g, int mode)
{
    const int n0 = g, n1 = g + 4, n2 = g + 8;
    float a0 = bias[h], a1 = a0, a2 = a0;
#pragma unroll
    for (int j = 0; j < NN; ++j) {
        float xv = s.xl[j * PAD + h];
        a0 = fmaf(s.e[n0 * NN + j], xv, a0);
        a1 = fmaf(s.e[n1 * NN + j], xv, a1);
        a2 = fmaf(s.e[n2 * NN + j], xv, a2);
    }
    if (mode == 1) {
        a0 += ALPHA * s.skipb[n0 * HID + h];
        a1 += ALPHA * s.skipb[n1 * HID + h];
        a2 += ALPHA * s.skipb[n2 * HID + h];
    }
    xout[n0 * HID + h] = fmaxf(a0, 0.f);
    xout[n1 * HID + h] = fmaxf(a1, 0.f);
    xout[n2 * HID + h] = fmaxf(a2, 0.f);
}

__global__ void __launch_bounds__(NTH, 1)
gae_kernel(const float* __restrict__ batch,
           const float* __restrict__ enc_w1, const float* __restrict__ enc_b1,
           const float* __restrict__ enc_w2, const float* __restrict__ enc_b2,
           const float* __restrict__ enc_w3, const float* __restrict__ enc_b3,
           const float* __restrict__ g1_wl, const float* __restrict__ g1_wr,
           const float* __restrict__ g1_att, const float* __restrict__ g1_b,
           const float* __restrict__ g2_wl, const float* __restrict__ g2_wr,
           const float* __restrict__ g2_att, const float* __restrict__ g2_b,
           const float* __restrict__ g3_wl, const float* __restrict__ g3_wr,
           const float* __restrict__ g3_att, const float* __restrict__ g3_b,
           const float* __restrict__ g4_wl, const float* __restrict__ g4_wr,
           const float* __restrict__ g4_att, const float* __restrict__ g4_b,
           const float* __restrict__ lab_w, const float* __restrict__ lab_b,
           const float* __restrict__ val_w, const float* __restrict__ val_b,
           const float* __restrict__ skip_w, const float* __restrict__ skip_b,
           float* __restrict__ out)
{
    extern __shared__ unsigned char smraw[];
    SM& S = *reinterpret_cast<SM*>(smraw);
    const int T = threadIdx.x;

    // ---- stage weights into shared once per block (transposed+padded for 64x64 mats) ----
    for (int i = T; i < HID * HID; i += NTH) {
        const int k = i >> 6, hh = i & 63;
        const int d = hh * PAD + k;
        S.w_enc2t[d] = enc_w2[i];
        S.wl2t[d] = g2_wl[i]; S.wr2t[d] = g2_wr[i];
        S.wl3t[d] = g3_wl[i]; S.wr3t[d] = g3_wr[i];
        S.wl4t[d] = g4_wl[i]; S.wr4t[d] = g4_wr[i];
    }
    for (int i = T; i < 5 * HID; i += NTH) S.w_enc1[i] = enc_w1[i];
    if (T < HID) {
        const int i = T;
        S.b_enc1[i] = enc_b1[i]; S.b_enc2[i] = enc_b2[i];
        S.g_wl1[i] = g1_wl[i];   S.g_wr1[i] = g1_wr[i];
        S.att1[i] = g1_att[i];   S.gb1[i] = g1_b[i];
        S.att2[i] = g2_att[i];   S.gb2[i] = g2_b[i];
        S.att3[i] = g3_att[i];   S.gb3[i] = g3_b[i];
        S.att4[i] = g4_att[i];   S.gb4[i] = g4_b[i];
        S.b_skip[i] = skip_b[i]; S.w_val[i] = val_w[i];
    } else if (T >= 128 && T < 128 + 3 * HID) {
        const int i = T - 128;
        S.w_enc3[i] = enc_w3[i]; S.w_skip[i] = skip_w[i];
    } else if (T >= 512 && T < 512 + 4 * HID) {
        S.w_lab[T - 512] = lab_w[T - 512];
    } else if (T >= 896 && T < 899) {
        S.b_enc3[T - 896] = enc_b3[T - 896];
    } else if (T >= 900 && T < 904) {
        S.b_lab[T - 900] = lab_b[T - 900];
    } else if (T == 904) {
        S.b_val[0] = val_b[0];
    }
    __syncthreads();

    const int sb  = T >> 8;
    const int tid = T & 255;
    SubS& s = S.sub[sb];
    const int h = tid & 63;
    const int g = tid >> 6;
    const int n0 = g, n1 = g + 4, n2 = g + 8;
    const int ai = tid / NN;        // valid when tid < 144
    const int aj = tid - ai * NN;
    const int b = blockIdx.x * NSUB + sb;

    // ---- phase 0: load input, emit passthrough ----
    if (tid < 60) {
        float v = batch[(size_t)b * 60 + tid];
        s.binp[tid] = v;
        int n = tid / 5, c = tid - n * 5;
        if (c < 4) out[O1 + (size_t)b * 48 + n * 4 + c] = v;
        else       out[O2 + (size_t)b * 12 + n] = v;
    }
    barsub(sb);

    // ---- encoder layer 1 (K=5) -> xbuf ----
    {
        float a0 = S.b_enc1[h], a1 = a0, a2 = a0;
#pragma unroll
        for (int k = 0; k < 5; ++k) {
            float w = S.w_enc1[k * HID + h];
            a0 = fmaf(s.binp[n0 * 5 + k], w, a0);
            a1 = fmaf(s.binp[n1 * 5 + k], w, a1);
            a2 = fmaf(s.binp[n2 * 5 + k], w, a2);
        }
        s.xbuf[n0 * HID + h] = fmaxf(a0, 0.f);
        s.xbuf[n1 * HID + h] = fmaxf(a1, 0.f);
        s.xbuf[n2 * HID + h] = fmaxf(a2, 0.f);
    }
    barsub(sb);

    // ---- encoder layer 2 -> xcur ----
    gemm64_relu(s.xbuf, S.w_enc2t, S.b_enc2, s.xcur, h, g);
    barsub(sb);

    // ---- latent (64 -> 3) + emit ----
    if (tid < 36) {
        int n = tid / 3, c = tid - n * 3;
        float a = S.b_enc3[c];
#pragma unroll
        for (int k = 0; k < 64; k += 2) {
            int k0 = (k + tid) & 63, k1 = (k + 1 + tid) & 63;
            a = fmaf(s.xcur[n * HID + k0], S.w_enc3[k0 * 3 + c], a);
            a = fmaf(s.xcur[n * HID + k1], S.w_enc3[k1 * 3 + c], a);
        }
        s.latent[n * 4 + c] = a;
        out[OT + (size_t)b * 36 + n * 3 + c] = a;
    }
    barsub(sb);

    // ---- Gabriel adjacency + skip projection ----
    if (tid < NN * NN) {
        float xi = s.latent[ai * 4], yi = s.latent[ai * 4 + 1];
        float xj = s.latent[aj * 4], yj = s.latent[aj * 4 + 1];
        float dx = xi - xj, dy = yi - yj;
        float r2 = (dx * dx + dy * dy) * 0.25f;
        float mx = (xi + xj) * 0.5f, my = (yi + yj) * 0.5f;
        int ok = 1;
#pragma unroll
        for (int k = 0; k < NN; ++k) {
            if (k == ai || k == aj) continue;
            float ax = s.latent[k * 4] - mx;
            float ay = s.latent[k * 4 + 1] - my;
            float d2 = ax * ax + ay * ay;
            ok &= (d2 > r2) ? 1 : 0;
        }
        s.gab[tid] = (ai != aj) ? ok : 0;
    }
    {
        float a0 = S.b_skip[h], a1 = a0, a2 = a0;
#pragma unroll
        for (int c = 0; c < 3; ++c) {
            float w = S.w_skip[c * HID + h];
            a0 = fmaf(s.latent[n0 * 4 + c], w, a0);
            a1 = fmaf(s.latent[n1 * 4 + c], w, a1);
            a2 = fmaf(s.latent[n2 * 4 + c], w, a2);
        }
        s.skipb[n0 * HID + h] = a0;
        s.skipb[n1 * HID + h] = a1;
        s.skipb[n2 * HID + h] = a2;
    }
    barsub(sb);

    // adjacency predicate, computed once, reused across all 4 GAT layers
    int adjv = 0;
    if (tid < NN * NN)
        adjv = s.gab[ai * NN + aj] | s.gab[aj * NN + ai] | (ai == aj ? 1 : 0);

    // ---- GAT 1 (cin=1, x0 = latent[:,2]) ----
    {
        float wl = S.g_wl1[h], wr = S.g_wr1[h];
        float v0 = s.latent[n0 * 4 + 2], v1 = s.latent[n1 * 4 + 2], v2 = s.latent[n2 * 4 + 2];
        s.xl[n0 * PAD + h] = v0 * wl; s.xr[n0 * PAD + h] = v0 * wr;
        s.xl[n1 * PAD + h] = v1 * wl; s.xr[n1 * PAD + h] = v1 * wr;
        s.xl[n2 * PAD + h] = v2 * wl; s.xr[n2 * PAD + h] = v2 * wr;
    }
    barsub(sb);
    gat_attn(s, S.att1, tid, ai, aj, adjv, sb);
    gat_agg(s, S.gb1, s.xcur, h, g, 0);
    barsub(sb);

    // ---- GAT 2 -> x2s ----
    dual_gemm64(s.xcur, S.wl2t, S.wr2t, s.xl, s.xr, h, g);
    barsub(sb);
    gat_attn(s, S.att2, tid, ai, aj, adjv, sb);
    gat_agg(s, S.gb2, s.x2s, h, g, 0);
    barsub(sb);

    // ---- GAT 3 -> xbuf ----
    dual_gemm64(s.x2s, S.wl3t, S.wr3t, s.xl, s.xr, h, g);
    barsub(sb);
    gat_attn(s, S.att3, tid, ai, aj, adjv, sb);
    gat_agg(s, S.gb3, s.xbuf, h, g, 1);
    barsub(sb);

    // ---- logits head (reads xbuf) + GAT4 projections ----
    dual_gemm64(s.x2s, S.wl4t, S.wr4t, s.xl, s.xr, h, g);
    if (tid < 48) {
        int n = tid / 4, c = tid - n * 4;
        float a = S.b_lab[c];
#pragma unroll
        for (int k = 0; k < 64; k += 2) {
            int k0 = (k + tid) & 63, k1 = (k + 1 + tid) & 63;
            a = fmaf(s.xbuf[n * HID + k0], S.w_lab[k0 * 4 + c], a);
            a = fmaf(s.xbuf[n * HID + k1], S.w_lab[k1 * 4 + c], a);
        }
        out[OL + (size_t)b * 48 + n * 4 + c] = a;
    }
    barsub(sb);

    // ---- GAT 4 -> xbuf (x4) ----
    gat_attn(s, S.att4, tid, ai, aj, adjv, sb);
    gat_agg(s, S.gb4, s.xbuf, h, g, 1);
    barsub(sb);

    // ---- values head ----
    if (tid < NN) {
        float a = S.b_val[0];
#pragma unroll
        for (int k = 0; k < 64; k += 2) {
            int k0 = (k + tid) & 63, k1 = (k + 1 + tid) & 63;
            a = fmaf(s.xbuf[tid * HID + k0], S.w_val[k0], a);
            a = fmaf(s.xbuf[tid * HID + k1], S.w_val[k1], a);
        }
        out[OV + (size_t)b * 12 + tid] = a;
    }
}

} // anonymous namespace

extern "C" void kernel_launch(void* const* d_in, const int* in_sizes, int n_in,
                              void* d_out, int out_size)
{
    const float* p[29];
    for (int i = 0; i < 29; ++i) p[i] = (const float*)d_in[i];
    float* out = (float*)d_out;

    cudaFuncSetAttribute(gae_kernel, cudaFuncAttributeMaxDynamicSharedMemorySize,
                         (int)sizeof(SM));

    gae_kernel<<<GRID, NTH, sizeof(SM)>>>(
        p[0],
        p[1], p[2], p[3], p[4], p[5], p[6],
        p[7], p[8], p[9], p[10],
        p[11], p[12], p[13], p[14],
        p[15], p[16], p[17], p[18],
        p[19], p[20], p[21], p[22],
        p[23], p[24], p[25], p[26], p[27], p[28],
        out);
}

// round 4
// speedup vs baseline: 1.8896x; 1.0521x over previous
#include <cuda_runtime.h>
#include <math.h>

namespace {

constexpr int   NN    = 12;
constexpr int   HID   = 64;
constexpr int   PAD   = 68;    // padded row stride (floats)
constexpr float SLOPE = 0.2f;
constexpr float ALPHA = 0.1f;
constexpr int   TPG   = 128;   // threads per graph
constexpr int   NSUB  = 4;     // graphs per block
constexpr int   NTH   = TPG * NSUB;   // 512
constexpr int   GRID  = 1024;  // 4096 graphs

// output section offsets (fp32 elements)
constexpr size_t O1 = 0;
constexpr size_t O2 = 196608;
constexpr size_t OL = 245760;
constexpr size_t OV = 442368;
constexpr size_t OT = 491520;

struct alignas(16) SubS {
    float binp[64];
    float xA  [NN * HID];     // activations ping
    float xC  [NN * HID];     // activations pong (x2 persists here)
    float xl  [NN * PAD];
    float xr  [NN * PAD];
    float latent[NN * 4];
    float e   [NN * NN];
    int   gab [NN * NN];
};

struct alignas(16) SM {
    float w_enc1[5 * HID],    b_enc1[HID];
    float w_enc2t[HID * PAD], b_enc2[HID];
    float w_enc3[HID * 3],    b_enc3[4];
    float g_wl1[HID], g_wr1[HID];
    float wl2t[HID * PAD], wr2t[HID * PAD];
    float wl3t[HID * PAD], wr3t[HID * PAD];
    float wl4t[HID * PAD], wr4t[HID * PAD];
    float att1[HID], att2[HID], att3[HID], att4[HID];
    float gb1[HID],  gb2[HID],  gb3[HID],  gb4[HID];
    float w_skip[3 * HID], b_skip[HID];
    float w_lab[HID * 4],  b_lab[4];
    float w_val[HID],      b_val[4];
    SubS  sub[NSUB];
};

__device__ __forceinline__ void barsub(int sb)
{
    asm volatile("bar.sync %0, %1;" :: "r"(sb + 1), "n"(TPG) : "memory");
}

__device__ __forceinline__ float lrelu(float v) { return fmaxf(v, SLOPE * v); }

// single-matrix 64x64 GEMM + relu, 6 rows per thread
__device__ __forceinline__ void gemm64_relu6(const float* __restrict__ X,
                                             const float* __restrict__ Wt,
                                             const float* __restrict__ bias,
                                             float* __restrict__ Y, int h, int gg)
{
    const int nb = gg * 6;
    float a[6];
    const float bv = bias[h];
#pragma unroll
    for (int r = 0; r < 6; ++r) a[r] = bv;
    const float4* Wp = (const float4*)(Wt + h * PAD);
    const float4* X4 = (const float4*)X;
#pragma unroll
    for (int k4 = 0; k4 < 16; ++k4) {
        float4 w = Wp[k4];
#pragma unroll
        for (int r = 0; r < 6; ++r) {
            float4 x = X4[(nb + r) * 16 + k4];
            a[r] = fmaf(x.x, w.x, a[r]); a[r] = fmaf(x.y, w.y, a[r]);
            a[r] = fmaf(x.z, w.z, a[r]); a[r] = fmaf(x.w, w.w, a[r]);
        }
    }
#pragma unroll
    for (int r = 0; r < 6; ++r) Y[(nb + r) * HID + h] = fmaxf(a[r], 0.f);
}

// dual 64x64 GEMM (no bias), 6 rows per thread, outputs stride PAD
__device__ __forceinline__ void dual_gemm6(const float* __restrict__ X,
                                           const float* __restrict__ WLt,
                                           const float* __restrict__ WRt,
                                           float* __restrict__ XL,
                                           float* __restrict__ XR, int h, int gg)
{
    const int nb = gg * 6;
    float l[6], r_[6];
#pragma unroll
    for (int r = 0; r < 6; ++r) { l[r] = 0.f; r_[r] = 0.f; }
    const float4* Lp = (const float4*)(WLt + h * PAD);
    const float4* Rp = (const float4*)(WRt + h * PAD);
    const float4* X4 = (const float4*)X;
#pragma unroll
    for (int k4 = 0; k4 < 16; ++k4) {
        float4 wl = Lp[k4];
        float4 wr = Rp[k4];
#pragma unroll
        for (int r = 0; r < 6; ++r) {
            float4 x = X4[(nb + r) * 16 + k4];
            l[r]  = fmaf(x.x, wl.x, l[r]);  l[r]  = fmaf(x.y, wl.y, l[r]);
            l[r]  = fmaf(x.z, wl.z, l[r]);  l[r]  = fmaf(x.w, wl.w, l[r]);
            r_[r] = fmaf(x.x, wr.x, r_[r]); r_[r] = fmaf(x.y, wr.y, r_[r]);
            r_[r] = fmaf(x.z, wr.z, r_[r]); r_[r] = fmaf(x.w, wr.w, r_[r]);
        }
    }
#pragma unroll
    for (int r = 0; r < 6; ++r) {
        XL[(nb + r) * PAD + h] = l[r];
        XR[(nb + r) * PAD + h] = r_[r];
    }
}

// attention scores + softmax (2 named barriers)
__device__ __forceinline__ void gat_attn(SubS& s, const float* __restrict__ attv,
                                         int tid, int sb)
{
    for (int p = tid; p < NN * NN; p += TPG) {
        const int i = p / NN, j = p - (p / NN) * NN;
        int adjv = s.gab[i * NN + j] | s.gab[j * NN + i] | (i == j ? 1 : 0);
        float acc = -1000000000.0f;
        if (adjv) {
            float a0 = 0.f, a1 = 0.f;
            const float4* xlj = (const float4*)(s.xl + j * PAD);
            const float4* xri = (const float4*)(s.xr + i * PAD);
            const float4* at4 = (const float4*)attv;
#pragma unroll
            for (int k = 0; k < 16; k += 2) {
                float4 l0 = xlj[k],     r0 = xri[k],     w0 = at4[k];
                float4 l1 = xlj[k + 1], r1 = xri[k + 1], w1 = at4[k + 1];
                a0 = fmaf(lrelu(l0.x + r0.x), w0.x, a0);
                a0 = fmaf(lrelu(l0.y + r0.y), w0.y, a0);
                a0 = fmaf(lrelu(l0.z + r0.z), w0.z, a0);
                a0 = fmaf(lrelu(l0.w + r0.w), w0.w, a0);
                a1 = fmaf(lrelu(l1.x + r1.x), w1.x, a1);
                a1 = fmaf(lrelu(l1.y + r1.y), w1.y, a1);
                a1 = fmaf(lrelu(l1.z + r1.z), w1.z, a1);
                a1 = fmaf(lrelu(l1.w + r1.w), w1.w, a1);
            }
            acc = a0 + a1;
        }
        s.e[p] = acc;
    }
    barsub(sb);
    if (tid < NN) {
        const int i = tid;
        float m = -3.4e38f;
#pragma unroll
        for (int j = 0; j < NN; ++j) m = fmaxf(m, s.e[i * NN + j]);
        float vals[NN];
        float ssum = 0.f;
#pragma unroll
        for (int j = 0; j < NN; ++j) {
            float v = __expf(s.e[i * NN + j] - m);
            vals[j] = v;
            ssum += v;
        }
        float r = 1.0f / ssum;
#pragma unroll
        for (int j = 0; j < NN; ++j) s.e[i * NN + j] = vals[j] * r;
    }
    barsub(sb);
}

// out[n,h] = relu(sum_j e[n,j]*xl[j,h] + bias [+ alpha*skip]), 6 rows/thread
__device__ __forceinline__ void gat_agg6(SubS& s, const float* __restrict__ bias,
                                         float* __restrict__ xout, int h, int gg,
                                         const float* skipreg, int mode)
{
    const int nb = gg * 6;
    float xv[NN];
#pragma unroll
    for (int j = 0; j < NN; ++j) xv[j] = s.xl[j * PAD + h];
    const float bv = bias[h];
#pragma unroll
    for (int r = 0; r < 6; ++r) {
        const float4* e4 = (const float4*)(s.e + (nb + r) * NN);
        float4 e0 = e4[0], e1 = e4[1], e2 = e4[2];
        float a = bv;
        a = fmaf(e0.x, xv[0], a);  a = fmaf(e0.y, xv[1], a);
        a = fmaf(e0.z, xv[2], a);  a = fmaf(e0.w, xv[3], a);
        a = fmaf(e1.x, xv[4], a);  a = fmaf(e1.y, xv[5], a);
        a = fmaf(e1.z, xv[6], a);  a = fmaf(e1.w, xv[7], a);
        a = fmaf(e2.x, xv[8], a);  a = fmaf(e2.y, xv[9], a);
        a = fmaf(e2.z, xv[10], a); a = fmaf(e2.w, xv[11], a);
        if (mode == 1) a += ALPHA * skipreg[r];
        xout[(nb + r) * HID + h] = fmaxf(a, 0.f);
    }
}

__global__ void __launch_bounds__(NTH, 1)
gae_kernel(const float* __restrict__ batch,
           const float* __restrict__ enc_w1, const float* __restrict__ enc_b1,
           const float* __restrict__ enc_w2, const float* __restrict__ enc_b2,
           const float* __restrict__ enc_w3, const float* __restrict__ enc_b3,
           const float* __restrict__ g1_wl, const float* __restrict__ g1_wr,
           const float* __restrict__ g1_att, const float* __restrict__ g1_b,
           const float* __restrict__ g2_wl, const float* __restrict__ g2_wr,
           const float* __restrict__ g2_att, const float* __restrict__ g2_b,
           const float* __restrict__ g3_wl, const float* __restrict__ g3_wr,
           const float* __restrict__ g3_att, const float* __restrict__ g3_b,
           const float* __restrict__ g4_wl, const float* __restrict__ g4_wr,
           const float* __restrict__ g4_att, const float* __restrict__ g4_b,
           const float* __restrict__ lab_w, const float* __restrict__ lab_b,
           const float* __restrict__ val_w, const float* __restrict__ val_b,
           const float* __restrict__ skip_w, const float* __restrict__ skip_b,
           float* __restrict__ out)
{
    extern __shared__ unsigned char smraw[];
    SM& S = *reinterpret_cast<SM*>(smraw);
    const int T = threadIdx.x;

    // ---- stage weights (strided loops, correct for any block size) ----
    for (int i = T; i < HID * HID; i += NTH) {
        const int k = i >> 6, hh = i & 63;
        const int d = hh * PAD + k;
        S.w_enc2t[d] = enc_w2[i];
        S.wl2t[d] = g2_wl[i]; S.wr2t[d] = g2_wr[i];
        S.wl3t[d] = g3_wl[i]; S.wr3t[d] = g3_wr[i];
        S.wl4t[d] = g4_wl[i]; S.wr4t[d] = g4_wr[i];
    }
    for (int i = T; i < 5 * HID; i += NTH) S.w_enc1[i] = enc_w1[i];
    for (int i = T; i < 4 * HID; i += NTH) S.w_lab[i] = lab_w[i];
    for (int i = T; i < 3 * HID; i += NTH) { S.w_enc3[i] = enc_w3[i]; S.w_skip[i] = skip_w[i]; }
    if (T < HID) {
        const int i = T;
        S.b_enc1[i] = enc_b1[i]; S.b_enc2[i] = enc_b2[i];
        S.g_wl1[i] = g1_wl[i];   S.g_wr1[i] = g1_wr[i];
        S.att1[i] = g1_att[i];   S.gb1[i] = g1_b[i];
        S.att2[i] = g2_att[i];   S.gb2[i] = g2_b[i];
        S.att3[i] = g3_att[i];   S.gb3[i] = g3_b[i];
        S.att4[i] = g4_att[i];   S.gb4[i] = g4_b[i];
        S.b_skip[i] = skip_b[i]; S.w_val[i] = val_w[i];
    } else if (T >= 64 && T < 67) {
        S.b_enc3[T - 64] = enc_b3[T - 64];
    } else if (T >= 68 && T < 72) {
        S.b_lab[T - 68] = lab_b[T - 68];
    } else if (T == 72) {
        S.b_val[0] = val_b[0];
    }
    __syncthreads();

    const int sb  = T / TPG;
    const int tid = T - sb * TPG;   // 0..127
    SubS& s = S.sub[sb];
    const int h  = tid & 63;
    const int gg = tid >> 6;        // 0 or 1
    const int nb = gg * 6;
    const int b = blockIdx.x * NSUB + sb;

    // ---- input + passthrough ----
    if (tid < 60) {
        float v = batch[(size_t)b * 60 + tid];
        s.binp[tid] = v;
        int n = tid / 5, c = tid - n * 5;
        if (c < 4) out[O1 + (size_t)b * 48 + n * 4 + c] = v;
        else       out[O2 + (size_t)b * 12 + n] = v;
    }
    barsub(sb);

    // ---- encoder layer 1 (K=5) -> xA ----
    {
        float a[6];
        const float bv = S.b_enc1[h];
#pragma unroll
        for (int r = 0; r < 6; ++r) a[r] = bv;
#pragma unroll
        for (int k = 0; k < 5; ++k) {
            float w = S.w_enc1[k * HID + h];
#pragma unroll
            for (int r = 0; r < 6; ++r)
                a[r] = fmaf(s.binp[(nb + r) * 5 + k], w, a[r]);
        }
#pragma unroll
        for (int r = 0; r < 6; ++r) s.xA[(nb + r) * HID + h] = fmaxf(a[r], 0.f);
    }
    barsub(sb);

    // ---- encoder layer 2 -> xC ----
    gemm64_relu6(s.xA, S.w_enc2t, S.b_enc2, s.xC, h, gg);
    barsub(sb);

    // ---- latent (64->3) + emit ----
    if (tid < 36) {
        int n = tid / 3, c = tid - n * 3;
        float a = S.b_enc3[c];
#pragma unroll
        for (int k = 0; k < 64; k += 2) {
            int k0 = (k + tid) & 63, k1 = (k + 1 + tid) & 63;
            a = fmaf(s.xC[n * HID + k0], S.w_enc3[k0 * 3 + c], a);
            a = fmaf(s.xC[n * HID + k1], S.w_enc3[k1 * 3 + c], a);
        }
        s.latent[n * 4 + c] = a;
        out[OT + (size_t)b * 36 + n * 3 + c] = a;
    }
    barsub(sb);

    // ---- Gabriel adjacency + skip projection (skip in registers) ----
    for (int p = tid; p < NN * NN; p += TPG) {
        const int i = p / NN, j = p - (p / NN) * NN;
        float xi = s.latent[i * 4], yi = s.latent[i * 4 + 1];
        float xj = s.latent[j * 4], yj = s.latent[j * 4 + 1];
        float dx = xi - xj, dy = yi - yj;
        float r2 = (dx * dx + dy * dy) * 0.25f;
        float mx = (xi + xj) * 0.5f, my = (yi + yj) * 0.5f;
        int ok = 1;
#pragma unroll
        for (int k = 0; k < NN; ++k) {
            if (k == i || k == j) continue;
            float ax = s.latent[k * 4] - mx;
            float ay = s.latent[k * 4 + 1] - my;
            float d2 = ax * ax + ay * ay;
            ok &= (d2 > r2) ? 1 : 0;
        }
        s.gab[p] = (i != j) ? ok : 0;
    }
    float skipreg[6];
    {
        const float bv = S.b_skip[h];
#pragma unroll
        for (int r = 0; r < 6; ++r) skipreg[r] = bv;
#pragma unroll
        for (int c = 0; c < 3; ++c) {
            float w = S.w_skip[c * HID + h];
#pragma unroll
            for (int r = 0; r < 6; ++r)
                skipreg[r] = fmaf(s.latent[(nb + r) * 4 + c], w, skipreg[r]);
        }
    }
    barsub(sb);

    // ---- GAT 1 (cin=1, x0 = latent[:,2]) ----
    {
        float wl = S.g_wl1[h], wr = S.g_wr1[h];
#pragma unroll
        for (int r = 0; r < 6; ++r) {
            float v = s.latent[(nb + r) * 4 + 2];
            s.xl[(nb + r) * PAD + h] = v * wl;
            s.xr[(nb + r) * PAD + h] = v * wr;
        }
    }
    barsub(sb);
    gat_attn(s, S.att1, tid, sb);
    gat_agg6(s, S.gb1, s.xA, h, gg, skipreg, 0);
    barsub(sb);

    // ---- GAT 2 -> xC (x2) ----
    dual_gemm6(s.xA, S.wl2t, S.wr2t, s.xl, s.xr, h, gg);
    barsub(sb);
    gat_attn(s, S.att2, tid, sb);
    gat_agg6(s, S.gb2, s.xC, h, gg, skipreg, 0);
    barsub(sb);

    // ---- GAT 3 -> xA (x3) ----
    dual_gemm6(s.xC, S.wl3t, S.wr3t, s.xl, s.xr, h, gg);
    barsub(sb);
    gat_attn(s, S.att3, tid, sb);
    gat_agg6(s, S.gb3, s.xA, h, gg, skipreg, 1);
    barsub(sb);

    // ---- GAT 4 projections + logits head (reads xA = x3) ----
    dual_gemm6(s.xC, S.wl4t, S.wr4t, s.xl, s.xr, h, gg);
    if (tid < 48) {
        int n = tid / 4, c = tid - n * 4;
        float a = S.b_lab[c];
#pragma unroll
        for (int k = 0; k < 64; k += 2) {
            int k0 = (k + tid) & 63, k1 = (k + 1 + tid) & 63;
            a = fmaf(s.xA[n * HID + k0], S.w_lab[k0 * 4 + c], a);
            a = fmaf(s.xA[n * HID + k1], S.w_lab[k1 * 4 + c], a);
        }
        out[OL + (size_t)b * 48 + n * 4 + c] = a;
    }
    barsub(sb);

    // ---- GAT 4 -> xA (x4) ----
    gat_attn(s, S.att4, tid, sb);
    gat_agg6(s, S.gb4, s.xA, h, gg, skipreg, 1);
    barsub(sb);

    // ---- values head ----
    if (tid < NN) {
        float a = S.b_val[0];
#pragma unroll
        for (int k = 0; k < 64; k += 2) {
            int k0 = (k + tid) & 63, k1 = (k + 1 + tid) & 63;
            a = fmaf(s.xA[tid * HID + k0], S.w_val[k0], a);
            a = fmaf(s.xA[tid * HID + k1], S.w_val[k1], a);
        }
        out[OV + (size_t)b * 12 + tid] = a;
    }
}

} // anonymous namespace

extern "C" void kernel_launch(void* const* d_in, const int* in_sizes, int n_in,
                              void* d_out, int out_size)
{
    const float* p[29];
    for (int i = 0; i < 29; ++i) p[i] = (const float*)d_in[i];
    float* out = (float*)d_out;

    cudaFuncSetAttribute(gae_kernel, cudaFuncAttributeMaxDynamicSharedMemorySize,
                         (int)sizeof(SM));

    gae_kernel<<<GRID, NTH, sizeof(SM)>>>(
        p[0],
        p[1], p[2], p[3], p[4], p[5], p[6],
        p[7], p[8], p[9], p[10],
        p[11], p[12], p[13], p[14],
        p[15], p[16], p[17], p[18],
        p[19], p[20], p[21], p[22],
        p[23], p[24], p[25], p[26], p[27], p[28],
        out);
}

// round 5
// speedup vs baseline: 2.0021x; 1.0595x over previous
#include <cuda_runtime.h>
#include <math.h>

namespace {

constexpr int   NN    = 12;
constexpr int   HID   = 64;
constexpr int   PAD   = 68;    // padded row stride (floats)
constexpr float SLOPE = 0.2f;
constexpr float ALPHA = 0.1f;
constexpr int   TPG   = 128;   // threads per graph
constexpr int   NSUB  = 6;     // graphs per block
constexpr int   NTH   = TPG * NSUB;   // 768
constexpr int   NB    = 4096;
constexpr int   GRID  = (NB + NSUB - 1) / NSUB;   // 683

// output section offsets (fp32 elements)
constexpr size_t O1 = 0;
constexpr size_t O2 = 196608;
constexpr size_t OL = 245760;
constexpr size_t OV = 442368;
constexpr size_t OT = 491520;

struct alignas(16) SubS {
    float binp[64];
    float xA  [NN * HID];     // activations ping
    float xC  [NN * HID];     // activations pong (x2 persists here)
    float xl  [NN * PAD];
    float xr  [NN * PAD];
    float latent[NN * 4];
    float e   [NN * NN];
};

struct alignas(16) SM {
    float w_enc1[5 * HID],    b_enc1[HID];
    float w_enc2t[HID * PAD], b_enc2[HID];
    float w_enc3[HID * 3],    b_enc3[4];
    float g_wl1[HID], g_wr1[HID];
    float wl2t[HID * PAD], wr2t[HID * PAD];
    float wl3t[HID * PAD], wr3t[HID * PAD];
    float wl4t[HID * PAD], wr4t[HID * PAD];
    float att1[HID], att2[HID], att3[HID], att4[HID];
    float gb1[HID],  gb2[HID],  gb3[HID],  gb4[HID];
    float w_skip[3 * HID], b_skip[HID];
    float w_lab[HID * 4],  b_lab[4];
    float w_val[HID],      b_val[4];
    SubS  sub[NSUB];
};

__device__ __forceinline__ void barsub(int sb)
{
    asm volatile("bar.sync %0, %1;" :: "r"(sb + 1), "n"(TPG) : "memory");
}

__device__ __forceinline__ float lrelu(float v) { return fmaxf(v, SLOPE * v); }

// single-matrix 64x64 GEMM + relu, 6 rows per thread
__device__ __forceinline__ void gemm64_relu6(const float* __restrict__ X,
                                             const float* __restrict__ Wt,
                                             const float* __restrict__ bias,
                                             float* __restrict__ Y, int h, int gg)
{
    const int nb = gg * 6;
    float a[6];
    const float bv = bias[h];
#pragma unroll
    for (int r = 0; r < 6; ++r) a[r] = bv;
    const float4* Wp = (const float4*)(Wt + h * PAD);
    const float4* X4 = (const float4*)X;
#pragma unroll
    for (int k4 = 0; k4 < 16; ++k4) {
        float4 w = Wp[k4];
#pragma unroll
        for (int r = 0; r < 6; ++r) {
            float4 x = X4[(nb + r) * 16 + k4];
            a[r] = fmaf(x.x, w.x, a[r]); a[r] = fmaf(x.y, w.y, a[r]);
            a[r] = fmaf(x.z, w.z, a[r]); a[r] = fmaf(x.w, w.w, a[r]);
        }
    }
#pragma unroll
    for (int r = 0; r < 6; ++r) Y[(nb + r) * HID + h] = fmaxf(a[r], 0.f);
}

// dual 64x64 GEMM (no bias), 6 rows per thread, outputs stride PAD
__device__ __forceinline__ void dual_gemm6(const float* __restrict__ X,
                                           const float* __restrict__ WLt,
                                           const float* __restrict__ WRt,
                                           float* __restrict__ XL,
                                           float* __restrict__ XR, int h, int gg)
{
    const int nb = gg * 6;
    float l[6], r_[6];
#pragma unroll
    for (int r = 0; r < 6; ++r) { l[r] = 0.f; r_[r] = 0.f; }
    const float4* Lp = (const float4*)(WLt + h * PAD);
    const float4* Rp = (const float4*)(WRt + h * PAD);
    const float4* X4 = (const float4*)X;
#pragma unroll
    for (int k4 = 0; k4 < 16; ++k4) {
        float4 wl = Lp[k4];
        float4 wr = Rp[k4];
#pragma unroll
        for (int r = 0; r < 6; ++r) {
            float4 x = X4[(nb + r) * 16 + k4];
            l[r]  = fmaf(x.x, wl.x, l[r]);  l[r]  = fmaf(x.y, wl.y, l[r]);
            l[r]  = fmaf(x.z, wl.z, l[r]);  l[r]  = fmaf(x.w, wl.w, l[r]);
            r_[r] = fmaf(x.x, wr.x, r_[r]); r_[r] = fmaf(x.y, wr.y, r_[r]);
            r_[r] = fmaf(x.z, wr.z, r_[r]); r_[r] = fmaf(x.w, wr.w, r_[r]);
        }
    }
#pragma unroll
    for (int r = 0; r < 6; ++r) {
        XL[(nb + r) * PAD + h] = l[r];
        XR[(nb + r) * PAD + h] = r_[r];
    }
}

// attention scores (adjacency in registers) + softmax (2 named barriers)
__device__ __forceinline__ void gat_attn(SubS& s, const float* __restrict__ attv,
                                         int tid, int sb, int adj0, int adj1)
{
#pragma unroll
    for (int rep = 0; rep < 2; ++rep) {
        const int p = tid + rep * TPG;
        if (p >= NN * NN) break;
        const int adjv = rep == 0 ? adj0 : adj1;
        const int i = p / NN, j = p - (p / NN) * NN;
        float acc = -1000000000.0f;
        if (adjv) {
            float a0 = 0.f, a1 = 0.f;
            const float4* xlj = (const float4*)(s.xl + j * PAD);
            const float4* xri = (const float4*)(s.xr + i * PAD);
            const float4* at4 = (const float4*)attv;
#pragma unroll
            for (int k = 0; k < 16; k += 2) {
                float4 l0 = xlj[k],     r0 = xri[k],     w0 = at4[k];
                float4 l1 = xlj[k + 1], r1 = xri[k + 1], w1 = at4[k + 1];
                a0 = fmaf(lrelu(l0.x + r0.x), w0.x, a0);
                a0 = fmaf(lrelu(l0.y + r0.y), w0.y, a0);
                a0 = fmaf(lrelu(l0.z + r0.z), w0.z, a0);
                a0 = fmaf(lrelu(l0.w + r0.w), w0.w, a0);
                a1 = fmaf(lrelu(l1.x + r1.x), w1.x, a1);
                a1 = fmaf(lrelu(l1.y + r1.y), w1.y, a1);
                a1 = fmaf(lrelu(l1.z + r1.z), w1.z, a1);
                a1 = fmaf(lrelu(l1.w + r1.w), w1.w, a1);
            }
            acc = a0 + a1;
        }
        s.e[p] = acc;
    }
    barsub(sb);
    if (tid < NN) {
        const int i = tid;
        float m = -3.4e38f;
#pragma unroll
        for (int j = 0; j < NN; ++j) m = fmaxf(m, s.e[i * NN + j]);
        float vals[NN];
        float ssum = 0.f;
#pragma unroll
        for (int j = 0; j < NN; ++j) {
            float v = __expf(s.e[i * NN + j] - m);
            vals[j] = v;
            ssum += v;
        }
        float r = 1.0f / ssum;
#pragma unroll
        for (int j = 0; j < NN; ++j) s.e[i * NN + j] = vals[j] * r;
    }
    barsub(sb);
}

// out[n,h] = relu(sum_j e[n,j]*xl[j,h] + bias [+ alpha*skip]), 6 rows/thread
__device__ __forceinline__ void gat_agg6(SubS& s, const float* __restrict__ bias,
                                         float* __restrict__ xout, int h, int gg,
                                         const float* skipreg, int mode)
{
    const int nb = gg * 6;
    float xv[NN];
#pragma unroll
    for (int j = 0; j < NN; ++j) xv[j] = s.xl[j * PAD + h];
    const float bv = bias[h];
#pragma unroll
    for (int r = 0; r < 6; ++r) {
        const float4* e4 = (const float4*)(s.e + (nb + r) * NN);
        float4 e0 = e4[0], e1 = e4[1], e2 = e4[2];
        float a = bv;
        a = fmaf(e0.x, xv[0], a);  a = fmaf(e0.y, xv[1], a);
        a = fmaf(e0.z, xv[2], a);  a = fmaf(e0.w, xv[3], a);
        a = fmaf(e1.x, xv[4], a);  a = fmaf(e1.y, xv[5], a);
        a = fmaf(e1.z, xv[6], a);  a = fmaf(e1.w, xv[7], a);
        a = fmaf(e2.x, xv[8], a);  a = fmaf(e2.y, xv[9], a);
        a = fmaf(e2.z, xv[10], a); a = fmaf(e2.w, xv[11], a);
        if (mode == 1) a += ALPHA * skipreg[r];
        xout[(nb + r) * HID + h] = fmaxf(a, 0.f);
    }
}

// Gabriel adjacency for pair p (symmetric: gab|gab^T == gab); latent in smem
__device__ __forceinline__ int gabriel_adj(const SubS& s, int p)
{
    const int i = p / NN, j = p - (p / NN) * NN;
    if (i == j) return 1;
    float xi = s.latent[i * 4], yi = s.latent[i * 4 + 1];
    float xj = s.latent[j * 4], yj = s.latent[j * 4 + 1];
    float dx = xi - xj, dy = yi - yj;
    float r2 = (dx * dx + dy * dy) * 0.25f;
    float mx = (xi + xj) * 0.5f, my = (yi + yj) * 0.5f;
    int ok = 1;
#pragma unroll
    for (int k = 0; k < NN; ++k) {
        if (k == i || k == j) continue;
        float ax = s.latent[k * 4] - mx;
        float ay = s.latent[k * 4 + 1] - my;
        float d2 = ax * ax + ay * ay;
        ok &= (d2 > r2) ? 1 : 0;
    }
    return ok;
}

__global__ void __launch_bounds__(NTH, 1)
gae_kernel(const float* __restrict__ batch,
           const float* __restrict__ enc_w1, const float* __restrict__ enc_b1,
           const float* __restrict__ enc_w2, const float* __restrict__ enc_b2,
           const float* __restrict__ enc_w3, const float* __restrict__ enc_b3,
           const float* __restrict__ g1_wl, const float* __restrict__ g1_wr,
           const float* __restrict__ g1_att, const float* __restrict__ g1_b,
           const float* __restrict__ g2_wl, const float* __restrict__ g2_wr,
           const float* __restrict__ g2_att, const float* __restrict__ g2_b,
           const float* __restrict__ g3_wl, const float* __restrict__ g3_wr,
           const float* __restrict__ g3_att, const float* __restrict__ g3_b,
           const float* __restrict__ g4_wl, const float* __restrict__ g4_wr,
           const float* __restrict__ g4_att, const float* __restrict__ g4_b,
           const float* __restrict__ lab_w, const float* __restrict__ lab_b,
           const float* __restrict__ val_w, const float* __restrict__ val_b,
           const float* __restrict__ skip_w, const float* __restrict__ skip_b,
           float* __restrict__ out)
{
    extern __shared__ unsigned char smraw[];
    SM& S = *reinterpret_cast<SM*>(smraw);
    const int T = threadIdx.x;

    // ---- stage weights (strided loops) ----
    for (int i = T; i < HID * HID; i += NTH) {
        const int k = i >> 6, hh = i & 63;
        const int d = hh * PAD + k;
        S.w_enc2t[d] = enc_w2[i];
        S.wl2t[d] = g2_wl[i]; S.wr2t[d] = g2_wr[i];
        S.wl3t[d] = g3_wl[i]; S.wr3t[d] = g3_wr[i];
        S.wl4t[d] = g4_wl[i]; S.wr4t[d] = g4_wr[i];
    }
    for (int i = T; i < 5 * HID; i += NTH) S.w_enc1[i] = enc_w1[i];
    for (int i = T; i < 4 * HID; i += NTH) S.w_lab[i] = lab_w[i];
    for (int i = T; i < 3 * HID; i += NTH) { S.w_enc3[i] = enc_w3[i]; S.w_skip[i] = skip_w[i]; }
    if (T < HID) {
        const int i = T;
        S.b_enc1[i] = enc_b1[i]; S.b_enc2[i] = enc_b2[i];
        S.g_wl1[i] = g1_wl[i];   S.g_wr1[i] = g1_wr[i];
        S.att1[i] = g1_att[i];   S.gb1[i] = g1_b[i];
        S.att2[i] = g2_att[i];   S.gb2[i] = g2_b[i];
        S.att3[i] = g3_att[i];   S.gb3[i] = g3_b[i];
        S.att4[i] = g4_att[i];   S.gb4[i] = g4_b[i];
        S.b_skip[i] = skip_b[i]; S.w_val[i] = val_w[i];
    } else if (T >= 64 && T < 67) {
        S.b_enc3[T - 64] = enc_b3[T - 64];
    } else if (T >= 68 && T < 72) {
        S.b_lab[T - 68] = lab_b[T - 68];
    } else if (T == 72) {
        S.b_val[0] = val_b[0];
    }
    __syncthreads();

    const int sb  = T / TPG;
    const int tid = T - sb * TPG;   // 0..127
    SubS& s = S.sub[sb];
    const int h  = tid & 63;
    const int gg = tid >> 6;        // 0 or 1
    const int nb = gg * 6;
    const int b = blockIdx.x * NSUB + sb;
    const bool active = (b < NB);

    // ---- input + passthrough ----
    if (active && tid < 60) {
        float v = batch[(size_t)b * 60 + tid];
        s.binp[tid] = v;
        int n = tid / 5, c = tid - n * 5;
        if (c < 4) out[O1 + (size_t)b * 48 + n * 4 + c] = v;
        else       out[O2 + (size_t)b * 12 + n] = v;
    }
    barsub(sb);

    // ---- encoder layer 1 (K=5) -> xA ----
    {
        float a[6];
        const float bv = S.b_enc1[h];
#pragma unroll
        for (int r = 0; r < 6; ++r) a[r] = bv;
#pragma unroll
        for (int k = 0; k < 5; ++k) {
            float w = S.w_enc1[k * HID + h];
#pragma unroll
            for (int r = 0; r < 6; ++r)
                a[r] = fmaf(s.binp[(nb + r) * 5 + k], w, a[r]);
        }
#pragma unroll
        for (int r = 0; r < 6; ++r) s.xA[(nb + r) * HID + h] = fmaxf(a[r], 0.f);
    }
    barsub(sb);

    // ---- encoder layer 2 -> xC ----
    gemm64_relu6(s.xA, S.w_enc2t, S.b_enc2, s.xC, h, gg);
    barsub(sb);

    // ---- latent (64->3) + emit ----
    if (tid < 36) {
        int n = tid / 3, c = tid - n * 3;
        float a = S.b_enc3[c];
#pragma unroll
        for (int k = 0; k < 64; k += 2) {
            int k0 = (k + tid) & 63, k1 = (k + 1 + tid) & 63;
            a = fmaf(s.xC[n * HID + k0], S.w_enc3[k0 * 3 + c], a);
            a = fmaf(s.xC[n * HID + k1], S.w_enc3[k1 * 3 + c], a);
        }
        s.latent[n * 4 + c] = a;
        if (active) out[OT + (size_t)b * 36 + n * 3 + c] = a;
    }
    barsub(sb);

    // ---- adjacency (registers, symmetric Gabriel) + skip (registers) + GAT1 proj ----
    const int adj0 = gabriel_adj(s, tid);
    const int adj1 = (tid < NN * NN - TPG) ? gabriel_adj(s, tid + TPG) : 0;
    float skipreg[6];
    {
        const float bv = S.b_skip[h];
#pragma unroll
        for (int r = 0; r < 6; ++r) skipreg[r] = bv;
#pragma unroll
        for (int c = 0; c < 3; ++c) {
            float w = S.w_skip[c * HID + h];
#pragma unroll
            for (int r = 0; r < 6; ++r)
                skipreg[r] = fmaf(s.latent[(nb + r) * 4 + c], w, skipreg[r]);
        }
    }
    {
        float wl = S.g_wl1[h], wr = S.g_wr1[h];
#pragma unroll
        for (int r = 0; r < 6; ++r) {
            float v = s.latent[(nb + r) * 4 + 2];
            s.xl[(nb + r) * PAD + h] = v * wl;
            s.xr[(nb + r) * PAD + h] = v * wr;
        }
    }
    barsub(sb);

    // ---- GAT 1 -> xA (x1) ----
    gat_attn(s, S.att1, tid, sb, adj0, adj1);
    gat_agg6(s, S.gb1, s.xA, h, gg, skipreg, 0);
    barsub(sb);

    // ---- GAT 2 -> xC (x2) ----
    dual_gemm6(s.xA, S.wl2t, S.wr2t, s.xl, s.xr, h, gg);
    barsub(sb);
    gat_attn(s, S.att2, tid, sb, adj0, adj1);
    gat_agg6(s, S.gb2, s.xC, h, gg, skipreg, 0);
    barsub(sb);

    // ---- GAT 3 -> xA (x3) ----
    dual_gemm6(s.xC, S.wl3t, S.wr3t, s.xl, s.xr, h, gg);
    barsub(sb);
    gat_attn(s, S.att3, tid, sb, adj0, adj1);
    gat_agg6(s, S.gb3, s.xA, h, gg, skipreg, 1);
    barsub(sb);

    // ---- GAT 4 projections (reads xC = x2) + logits head (reads xA = x3) ----
    dual_gemm6(s.xC, S.wl4t, S.wr4t, s.xl, s.xr, h, gg);
    if (active && tid < 48) {
        int n = tid / 4, c = tid - n * 4;
        float a = S.b_lab[c];
#pragma unroll
        for (int k = 0; k < 64; k += 2) {
            int k0 = (k + tid) & 63, k1 = (k + 1 + tid) & 63;
            a = fmaf(s.xA[n * HID + k0], S.w_lab[k0 * 4 + c], a);
            a = fmaf(s.xA[n * HID + k1], S.w_lab[k1 * 4 + c], a);
        }
        out[OL + (size_t)b * 48 + n * 4 + c] = a;
    }
    barsub(sb);

    // ---- GAT 4 -> xA (x4) ----
    gat_attn(s, S.att4, tid, sb, adj0, adj1);
    gat_agg6(s, S.gb4, s.xA, h, gg, skipreg, 1);
    barsub(sb);

    // ---- values head ----
    if (active && tid < NN) {
        float a = S.b_val[0];
#pragma unroll
        for (int k = 0; k < 64; k += 2) {
            int k0 = (k + tid) & 63, k1 = (k + 1 + tid) & 63;
            a = fmaf(s.xA[tid * HID + k0], S.w_val[k0], a);
            a = fmaf(s.xA[tid * HID + k1], S.w_val[k1], a);
        }
        out[OV + (size_t)b * 12 + tid] = a;
    }
}

} // anonymous namespace

extern "C" void kernel_launch(void* const* d_in, const int* in_sizes, int n_in,
                              void* d_out, int out_size)
{
    const float* p[29];
    for (int i = 0; i < 29; ++i) p[i] = (const float*)d_in[i];
    float* out = (float*)d_out;

    cudaFuncSetAttribute(gae_kernel, cudaFuncAttributeMaxDynamicSharedMemorySize,
                         (int)sizeof(SM));

    gae_kernel<<<GRID, NTH, sizeof(SM)>>>(
        p[0],
        p[1], p[2], p[3], p[4], p[5], p[6],
        p[7], p[8], p[9], p[10],
        p[11], p[12], p[13], p[14],
        p[15], p[16], p[17], p[18],
        p[19], p[20], p[21], p[22],
        p[23], p[24], p[25], p[26], p[27], p[28],
        out);
}

// round 6
// speedup vs baseline: 2.2038x; 1.1008x over previous
#include <cuda_runtime.h>
#include <math.h>

namespace {

constexpr int   NN    = 12;
constexpr int   HID   = 64;
constexpr int   PAD   = 68;    // padded row stride (floats)
constexpr float SLOPE = 0.2f;
constexpr float ALPHA = 0.1f;
constexpr int   TPG   = 128;   // threads per graph
constexpr int   NSUB  = 7;     // graphs per block
constexpr int   NTH   = TPG * NSUB;   // 896
constexpr int   NB    = 4096;
constexpr int   GRID  = (NB + NSUB - 1) / NSUB;   // 586

// output section offsets (fp32 elements)
constexpr size_t O1 = 0;
constexpr size_t O2 = 196608;
constexpr size_t OL = 245760;
constexpr size_t OV = 442368;
constexpr size_t OT = 491520;

struct alignas(16) SubS {
    float binp[64];
    float xA  [NN * HID];     // activations ping
    float xC  [NN * HID];     // activations pong (x2 persists here)
    float xl  [NN * PAD];
    float xr  [NN * PAD];
    float latent[NN * 4];
    float e   [NN * NN];      // exp(scores), unnormalized
};

struct alignas(16) SM {
    float w_enc1[5 * HID],    b_enc1[HID];
    float w_enc2t[HID * PAD], b_enc2[HID];
    float w_enc3[HID * 3],    b_enc3[4];
    float g_wl1[HID], g_wr1[HID];
    float wl2t[HID * PAD], wr2t[HID * PAD];
    float wl3t[HID * PAD], wr3t[HID * PAD];
    float wl4t[HID * PAD], wr4t[HID * PAD];
    float att1[HID], att2[HID], att3[HID], att4[HID];
    float gb1[HID],  gb2[HID],  gb3[HID],  gb4[HID];
    float w_skip[3 * HID], b_skip[HID];
    float w_lab[HID * 4],  b_lab[4];
    float w_val[HID],      b_val[4];
    SubS  sub[NSUB];
};

__device__ __forceinline__ void barsub(int sb)
{
    asm volatile("bar.sync %0, %1;" :: "r"(sb + 1), "n"(TPG) : "memory");
}

__device__ __forceinline__ float lrelu(float v) { return fmaxf(v, SLOPE * v); }

// single-matrix 64x64 GEMM + relu, 6 rows per thread
__device__ __forceinline__ void gemm64_relu6(const float* __restrict__ X,
                                             const float* __restrict__ Wt,
                                             const float* __restrict__ bias,
                                             float* __restrict__ Y, int h, int gg)
{
    const int nb = gg * 6;
    float a[6];
    const float bv = bias[h];
#pragma unroll
    for (int r = 0; r < 6; ++r) a[r] = bv;
    const float4* Wp = (const float4*)(Wt + h * PAD);
    const float4* X4 = (const float4*)X;
#pragma unroll
    for (int k4 = 0; k4 < 16; ++k4) {
        float4 w = Wp[k4];
#pragma unroll
        for (int r = 0; r < 6; ++r) {
            float4 x = X4[(nb + r) * 16 + k4];
            a[r] = fmaf(x.x, w.x, a[r]); a[r] = fmaf(x.y, w.y, a[r]);
            a[r] = fmaf(x.z, w.z, a[r]); a[r] = fmaf(x.w, w.w, a[r]);
        }
    }
#pragma unroll
    for (int r = 0; r < 6; ++r) Y[(nb + r) * HID + h] = fmaxf(a[r], 0.f);
}

// dual 64x64 GEMM (no bias), 6 rows per thread, outputs stride PAD
__device__ __forceinline__ void dual_gemm6(const float* __restrict__ X,
                                           const float* __restrict__ WLt,
                                           const float* __restrict__ WRt,
                                           float* __restrict__ XL,
                                           float* __restrict__ XR, int h, int gg)
{
    const int nb = gg * 6;
    float l[6], r_[6];
#pragma unroll
    for (int r = 0; r < 6; ++r) { l[r] = 0.f; r_[r] = 0.f; }
    const float4* Lp = (const float4*)(WLt + h * PAD);
    const float4* Rp = (const float4*)(WRt + h * PAD);
    const float4* X4 = (const float4*)X;
#pragma unroll
    for (int k4 = 0; k4 < 16; ++k4) {
        float4 wl = Lp[k4];
        float4 wr = Rp[k4];
#pragma unroll
        for (int r = 0; r < 6; ++r) {
            float4 x = X4[(nb + r) * 16 + k4];
            l[r]  = fmaf(x.x, wl.x, l[r]);  l[r]  = fmaf(x.y, wl.y, l[r]);
            l[r]  = fmaf(x.z, wl.z, l[r]);  l[r]  = fmaf(x.w, wl.w, l[r]);
            r_[r] = fmaf(x.x, wr.x, r_[r]); r_[r] = fmaf(x.y, wr.y, r_[r]);
            r_[r] = fmaf(x.z, wr.z, r_[r]); r_[r] = fmaf(x.w, wr.w, r_[r]);
        }
    }
#pragma unroll
    for (int r = 0; r < 6; ++r) {
        XL[(nb + r) * PAD + h] = l[r];
        XR[(nb + r) * PAD + h] = r_[r];
    }
}

// attention scores -> e[p] = adj ? exp(score) : 0   (no softmax pass; normalized in agg)
__device__ __forceinline__ void gat_scores(SubS& s, const float* __restrict__ attv,
                                           int tid, int adj0, int adj1)
{
#pragma unroll
    for (int rep = 0; rep < 2; ++rep) {
        const int p = tid + rep * TPG;
        if (p >= NN * NN) break;
        const int adjv = rep == 0 ? adj0 : adj1;
        const int i = p / NN, j = p - (p / NN) * NN;
        float ev = 0.0f;
        if (adjv) {
            float a0 = 0.f, a1 = 0.f;
            const float4* xlj = (const float4*)(s.xl + j * PAD);
            const float4* xri = (const float4*)(s.xr + i * PAD);
            const float4* at4 = (const float4*)attv;
#pragma unroll
            for (int k = 0; k < 16; k += 2) {
                float4 l0 = xlj[k],     r0 = xri[k],     w0 = at4[k];
                float4 l1 = xlj[k + 1], r1 = xri[k + 1], w1 = at4[k + 1];
                a0 = fmaf(lrelu(l0.x + r0.x), w0.x, a0);
                a0 = fmaf(lrelu(l0.y + r0.y), w0.y, a0);
                a0 = fmaf(lrelu(l0.z + r0.z), w0.z, a0);
                a0 = fmaf(lrelu(l0.w + r0.w), w0.w, a0);
                a1 = fmaf(lrelu(l1.x + r1.x), w1.x, a1);
                a1 = fmaf(lrelu(l1.y + r1.y), w1.y, a1);
                a1 = fmaf(lrelu(l1.z + r1.z), w1.z, a1);
                a1 = fmaf(lrelu(l1.w + r1.w), w1.w, a1);
            }
            ev = __expf(a0 + a1);
        }
        s.e[p] = ev;
    }
}

// out[n,h] = relu( (sum_j e[n,j]*xl[j,h]) / rowsum + bias [+ alpha*skip] ), 6 rows/thread
__device__ __forceinline__ void gat_agg6(SubS& s, const float* __restrict__ bias,
                                         float* __restrict__ xout, int h, int gg,
                                         const float* skipreg, int mode)
{
    const int nb = gg * 6;
    float xv[NN];
#pragma unroll
    for (int j = 0; j < NN; ++j) xv[j] = s.xl[j * PAD + h];
    const float bv = bias[h];
#pragma unroll
    for (int r = 0; r < 6; ++r) {
        const float4* e4 = (const float4*)(s.e + (nb + r) * NN);
        float4 e0 = e4[0], e1 = e4[1], e2 = e4[2];
        float rs = ((e0.x + e0.y) + (e0.z + e0.w))
                 + ((e1.x + e1.y) + (e1.z + e1.w))
                 + ((e2.x + e2.y) + (e2.z + e2.w));
        float a = 0.f;
        a = fmaf(e0.x, xv[0], a);  a = fmaf(e0.y, xv[1], a);
        a = fmaf(e0.z, xv[2], a);  a = fmaf(e0.w, xv[3], a);
        a = fmaf(e1.x, xv[4], a);  a = fmaf(e1.y, xv[5], a);
        a = fmaf(e1.z, xv[6], a);  a = fmaf(e1.w, xv[7], a);
        a = fmaf(e2.x, xv[8], a);  a = fmaf(e2.y, xv[9], a);
        a = fmaf(e2.z, xv[10], a); a = fmaf(e2.w, xv[11], a);
        a = fmaf(a, __frcp_rn(rs), bv);
        if (mode == 1) a += ALPHA * skipreg[r];
        xout[(nb + r) * HID + h] = fmaxf(a, 0.f);
    }
}

// Gabriel adjacency for pair p (symmetric); latent in smem
__device__ __forceinline__ int gabriel_adj(const SubS& s, int p)
{
    const int i = p / NN, j = p - (p / NN) * NN;
    if (i == j) return 1;
    float xi = s.latent[i * 4], yi = s.latent[i * 4 + 1];
    float xj = s.latent[j * 4], yj = s.latent[j * 4 + 1];
    float dx = xi - xj, dy = yi - yj;
    float r2 = (dx * dx + dy * dy) * 0.25f;
    float mx = (xi + xj) * 0.5f, my = (yi + yj) * 0.5f;
    int ok = 1;
#pragma unroll
    for (int k = 0; k < NN; ++k) {
        if (k == i || k == j) continue;
        float ax = s.latent[k * 4] - mx;
        float ay = s.latent[k * 4 + 1] - my;
        float d2 = ax * ax + ay * ay;
        ok &= (d2 > r2) ? 1 : 0;
    }
    return ok;
}

__global__ void __launch_bounds__(NTH, 1)
gae_kernel(const float* __restrict__ batch,
           const float* __restrict__ enc_w1, const float* __restrict__ enc_b1,
           const float* __restrict__ enc_w2, const float* __restrict__ enc_b2,
           const float* __restrict__ enc_w3, const float* __restrict__ enc_b3,
           const float* __restrict__ g1_wl, const float* __restrict__ g1_wr,
           const float* __restrict__ g1_att, const float* __restrict__ g1_b,
           const float* __restrict__ g2_wl, const float* __restrict__ g2_wr,
           const float* __restrict__ g2_att, const float* __restrict__ g2_b,
           const float* __restrict__ g3_wl, const float* __restrict__ g3_wr,
           const float* __restrict__ g3_att, const float* __restrict__ g3_b,
           const float* __restrict__ g4_wl, const float* __restrict__ g4_wr,
           const float* __restrict__ g4_att, const float* __restrict__ g4_b,
           const float* __restrict__ lab_w, const float* __restrict__ lab_b,
           const float* __restrict__ val_w, const float* __restrict__ val_b,
           const float* __restrict__ skip_w, const float* __restrict__ skip_b,
           float* __restrict__ out)
{
    extern __shared__ unsigned char smraw[];
    SM& S = *reinterpret_cast<SM*>(smraw);
    const int T = threadIdx.x;

    // ---- stage weights (strided loops) ----
    for (int i = T; i < HID * HID; i += NTH) {
        const int k = i >> 6, hh = i & 63;
        const int d = hh * PAD + k;
        S.w_enc2t[d] = enc_w2[i];
        S.wl2t[d] = g2_wl[i]; S.wr2t[d] = g2_wr[i];
        S.wl3t[d] = g3_wl[i]; S.wr3t[d] = g3_wr[i];
        S.wl4t[d] = g4_wl[i]; S.wr4t[d] = g4_wr[i];
    }
    for (int i = T; i < 5 * HID; i += NTH) S.w_enc1[i] = enc_w1[i];
    for (int i = T; i < 4 * HID; i += NTH) S.w_lab[i] = lab_w[i];
    for (int i = T; i < 3 * HID; i += NTH) { S.w_enc3[i] = enc_w3[i]; S.w_skip[i] = skip_w[i]; }
    if (T < HID) {
        const int i = T;
        S.b_enc1[i] = enc_b1[i]; S.b_enc2[i] = enc_b2[i];
        S.g_wl1[i] = g1_wl[i];   S.g_wr1[i] = g1_wr[i];
        S.att1[i] = g1_att[i];   S.gb1[i] = g1_b[i];
        S.att2[i] = g2_att[i];   S.gb2[i] = g2_b[i];
        S.att3[i] = g3_att[i];   S.gb3[i] = g3_b[i];
        S.att4[i] = g4_att[i];   S.gb4[i] = g4_b[i];
        S.b_skip[i] = skip_b[i]; S.w_val[i] = val_w[i];
    } else if (T >= 64 && T < 67) {
        S.b_enc3[T - 64] = enc_b3[T - 64];
    } else if (T >= 68 && T < 72) {
        S.b_lab[T - 68] = lab_b[T - 68];
    } else if (T == 72) {
        S.b_val[0] = val_b[0];
    }
    __syncthreads();

    const int sb  = T / TPG;
    const int tid = T - sb * TPG;   // 0..127
    SubS& s = S.sub[sb];
    const int h  = tid & 63;
    const int gg = tid >> 6;        // 0 or 1
    const int nb = gg * 6;
    const int b = blockIdx.x * NSUB + sb;
    const bool active = (b < NB);

    // ---- input + passthrough ----
    if (active && tid < 60) {
        float v = batch[(size_t)b * 60 + tid];
        s.binp[tid] = v;
        int n = tid / 5, c = tid - n * 5;
        if (c < 4) out[O1 + (size_t)b * 48 + n * 4 + c] = v;
        else       out[O2 + (size_t)b * 12 + n] = v;
    }
    barsub(sb);

    // ---- encoder layer 1 (K=5) -> xA ----
    {
        float a[6];
        const float bv = S.b_enc1[h];
#pragma unroll
        for (int r = 0; r < 6; ++r) a[r] = bv;
#pragma unroll
        for (int k = 0; k < 5; ++k) {
            float w = S.w_enc1[k * HID + h];
#pragma unroll
            for (int r = 0; r < 6; ++r)
                a[r] = fmaf(s.binp[(nb + r) * 5 + k], w, a[r]);
        }
#pragma unroll
        for (int r = 0; r < 6; ++r) s.xA[(nb + r) * HID + h] = fmaxf(a[r], 0.f);
    }
    barsub(sb);

    // ---- encoder layer 2 -> xC ----
    gemm64_relu6(s.xA, S.w_enc2t, S.b_enc2, s.xC, h, gg);
    barsub(sb);

    // ---- latent (64->3) + emit ----
    if (tid < 36) {
        int n = tid / 3, c = tid - n * 3;
        float a = S.b_enc3[c];
#pragma unroll
        for (int k = 0; k < 64; k += 2) {
            int k0 = (k + tid) & 63, k1 = (k + 1 + tid) & 63;
            a = fmaf(s.xC[n * HID + k0], S.w_enc3[k0 * 3 + c], a);
            a = fmaf(s.xC[n * HID + k1], S.w_enc3[k1 * 3 + c], a);
        }
        s.latent[n * 4 + c] = a;
        if (active) out[OT + (size_t)b * 36 + n * 3 + c] = a;
    }
    barsub(sb);

    // ---- adjacency (registers) + skip (registers) + GAT1 projections ----
    const int adj0 = gabriel_adj(s, tid);
    const int adj1 = (tid < NN * NN - TPG) ? gabriel_adj(s, tid + TPG) : 0;
    float skipreg[6];
    {
        const float bv = S.b_skip[h];
#pragma unroll
        for (int r = 0; r < 6; ++r) skipreg[r] = bv;
#pragma unroll
        for (int c = 0; c < 3; ++c) {
            float w = S.w_skip[c * HID + h];
#pragma unroll
            for (int r = 0; r < 6; ++r)
                skipreg[r] = fmaf(s.latent[(nb + r) * 4 + c], w, skipreg[r]);
        }
    }
    {
        float wl = S.g_wl1[h], wr = S.g_wr1[h];
#pragma unroll
        for (int r = 0; r < 6; ++r) {
            float v = s.latent[(nb + r) * 4 + 2];
            s.xl[(nb + r) * PAD + h] = v * wl;
            s.xr[(nb + r) * PAD + h] = v * wr;
        }
    }
    barsub(sb);

    // ---- GAT 1 -> xA (x1) ----
    gat_scores(s, S.att1, tid, adj0, adj1);
    barsub(sb);
    gat_agg6(s, S.gb1, s.xA, h, gg, skipreg, 0);
    barsub(sb);

    // ---- GAT 2 -> xC (x2) ----
    dual_gemm6(s.xA, S.wl2t, S.wr2t, s.xl, s.xr, h, gg);
    barsub(sb);
    gat_scores(s, S.att2, tid, adj0, adj1);
    barsub(sb);
    gat_agg6(s, S.gb2, s.xC, h, gg, skipreg, 0);
    barsub(sb);

    // ---- GAT 3 -> xA (x3) ----
    dual_gemm6(s.xC, S.wl3t, S.wr3t, s.xl, s.xr, h, gg);
    barsub(sb);
    gat_scores(s, S.att3, tid, adj0, adj1);
    barsub(sb);
    gat_agg6(s, S.gb3, s.xA, h, gg, skipreg, 1);
    barsub(sb);

    // ---- GAT 4 projections (reads xC = x2) + logits head (reads xA = x3) ----
    dual_gemm6(s.xC, S.wl4t, S.wr4t, s.xl, s.xr, h, gg);
    if (active && tid < 48) {
        int n = tid / 4, c = tid - n * 4;
        float a = S.b_lab[c];
#pragma unroll
        for (int k = 0; k < 64; k += 2) {
            int k0 = (k + tid) & 63, k1 = (k + 1 + tid) & 63;
            a = fmaf(s.xA[n * HID + k0], S.w_lab[k0 * 4 + c], a);
            a = fmaf(s.xA[n * HID + k1], S.w_lab[k1 * 4 + c], a);
        }
        out[OL + (size_t)b * 48 + n * 4 + c] = a;
    }
    barsub(sb);

    // ---- GAT 4 -> xA (x4) ----
    gat_scores(s, S.att4, tid, adj0, adj1);
    barsub(sb);
    gat_agg6(s, S.gb4, s.xA, h, gg, skipreg, 1);
    barsub(sb);

    // ---- values head ----
    if (active && tid < NN) {
        float a = S.b_val[0];
#pragma unroll
        for (int k = 0; k < 64; k += 2) {
            int k0 = (k + tid) & 63, k1 = (k + 1 + tid) & 63;
            a = fmaf(s.xA[tid * HID + k0], S.w_val[k0], a);
            a = fmaf(s.xA[tid * HID + k1], S.w_val[k1], a);
        }
        out[OV + (size_t)b * 12 + tid] = a;
    }
}

} // anonymous namespace

extern "C" void kernel_launch(void* const* d_in, const int* in_sizes, int n_in,
                              void* d_out, int out_size)
{
    const float* p[29];
    for (int i = 0; i < 29; ++i) p[i] = (const float*)d_in[i];
    float* out = (float*)d_out;

    cudaFuncSetAttribute(gae_kernel, cudaFuncAttributeMaxDynamicSharedMemorySize,
                         (int)sizeof(SM));

    gae_kernel<<<GRID, NTH, sizeof(SM)>>>(
        p[0],
        p[1], p[2], p[3], p[4], p[5], p[6],
        p[7], p[8], p[9], p[10],
        p[11], p[12], p[13], p[14],
        p[15], p[16], p[17], p[18],
        p[19], p[20], p[21], p[22],
        p[23], p[24], p[25], p[26], p[27], p[28],
        out);
}

// round 7
// speedup vs baseline: 2.2540x; 1.0228x over previous
#include <cuda_runtime.h>
#include <math.h>

namespace {

constexpr int   NN    = 12;
constexpr int   HID   = 64;
constexpr int   PAD   = 68;    // padded row stride (floats)
constexpr float SLOPE = 0.2f;
constexpr float ALPHA = 0.1f;
constexpr int   TPG   = 128;   // threads per graph
constexpr int   NSUB  = 7;     // graphs per block
constexpr int   NTH   = TPG * NSUB;   // 896
constexpr int   NB    = 4096;
constexpr int   GRID  = (NB + NSUB - 1) / NSUB;   // 586

// output section offsets (fp32 elements)
constexpr size_t O1 = 0;
constexpr size_t O2 = 196608;
constexpr size_t OL = 245760;
constexpr size_t OV = 442368;
constexpr size_t OT = 491520;

typedef unsigned long long u64;

__device__ __forceinline__ u64 ffma2(u64 a, u64 b, u64 c)
{
    u64 d;
    asm("fma.rn.f32x2 %0, %1, %2, %3;" : "=l"(d) : "l"(a), "l"(b), "l"(c));
    return d;
}

__device__ __forceinline__ float2 unpack2(u64 v)
{
    float2 f;
    asm("mov.b64 {%0, %1}, %2;" : "=f"(f.x), "=f"(f.y) : "l"(v));
    return f;
}

struct alignas(16) SubS {
    float binp[64];
    float xA  [NN * HID];     // activations ping
    float xC  [NN * HID];     // activations pong (x2 persists here)
    float xl  [NN * PAD];
    float xr  [NN * PAD];
    float latent[NN * 4];
    float e   [NN * NN];      // exp(scores), unnormalized
};

struct alignas(16) SM {
    float w_enc1[5 * HID],    b_enc1[HID];
    float w_enc2t[HID * PAD], b_enc2[HID];
    float w_enc3[HID * 3],    b_enc3[4];
    float g_wl1[HID], g_wr1[HID];
    float wl2t[HID * PAD], wr2t[HID * PAD];
    float wl3t[HID * PAD], wr3t[HID * PAD];
    float wl4t[HID * PAD], wr4t[HID * PAD];
    float att1[HID], att2[HID], att3[HID], att4[HID];
    float gb1[HID],  gb2[HID],  gb3[HID],  gb4[HID];
    float w_skip[3 * HID], b_skip[HID];
    float w_lab[HID * 4],  b_lab[4];
    float w_val[HID],      b_val[4];
    SubS  sub[NSUB];
};

__device__ __forceinline__ void barsub(int sb)
{
    asm volatile("bar.sync %0, %1;" :: "r"(sb + 1), "n"(TPG) : "memory");
}

__device__ __forceinline__ float lrelu(float v) { return fmaxf(v, SLOPE * v); }

// single-matrix 64x64 GEMM + relu, 6 rows/thread, packed f32x2 FMA
__device__ __forceinline__ void gemm64_relu6(const float* __restrict__ X,
                                             const float* __restrict__ Wt,
                                             const float* __restrict__ bias,
                                             float* __restrict__ Y, int h, int gg)
{
    const int nb = gg * 6;
    u64 acc[6];
#pragma unroll
    for (int r = 0; r < 6; ++r) acc[r] = 0ull;
    const ulonglong2* Wp = (const ulonglong2*)(Wt + h * PAD);
    const ulonglong2* X4 = (const ulonglong2*)X;
#pragma unroll
    for (int k4 = 0; k4 < 16; ++k4) {
        ulonglong2 w = Wp[k4];
#pragma unroll
        for (int r = 0; r < 6; ++r) {
            ulonglong2 x = X4[(nb + r) * 16 + k4];
            acc[r] = ffma2(x.x, w.x, acc[r]);
            acc[r] = ffma2(x.y, w.y, acc[r]);
        }
    }
    const float bv = bias[h];
#pragma unroll
    for (int r = 0; r < 6; ++r) {
        float2 f = unpack2(acc[r]);
        Y[(nb + r) * HID + h] = fmaxf(bv + (f.x + f.y), 0.f);
    }
}

// dual 64x64 GEMM (no bias), 6 rows/thread, packed f32x2 FMA, outputs stride PAD
__device__ __forceinline__ void dual_gemm6(const float* __restrict__ X,
                                           const float* __restrict__ WLt,
                                           const float* __restrict__ WRt,
                                           float* __restrict__ XL,
                                           float* __restrict__ XR, int h, int gg)
{
    const int nb = gg * 6;
    u64 accL[6], accR[6];
#pragma unroll
    for (int r = 0; r < 6; ++r) { accL[r] = 0ull; accR[r] = 0ull; }
    const ulonglong2* Lp = (const ulonglong2*)(WLt + h * PAD);
    const ulonglong2* Rp = (const ulonglong2*)(WRt + h * PAD);
    const ulonglong2* X4 = (const ulonglong2*)X;
#pragma unroll
    for (int k4 = 0; k4 < 16; ++k4) {
        ulonglong2 wl = Lp[k4];
        ulonglong2 wr = Rp[k4];
#pragma unroll
        for (int r = 0; r < 6; ++r) {
            ulonglong2 x = X4[(nb + r) * 16 + k4];
            accL[r] = ffma2(x.x, wl.x, accL[r]);
            accL[r] = ffma2(x.y, wl.y, accL[r]);
            accR[r] = ffma2(x.x, wr.x, accR[r]);
            accR[r] = ffma2(x.y, wr.y, accR[r]);
        }
    }
#pragma unroll
    for (int r = 0; r < 6; ++r) {
        float2 fl = unpack2(accL[r]);
        float2 fr = unpack2(accR[r]);
        XL[(nb + r) * PAD + h] = fl.x + fl.y;
        XR[(nb + r) * PAD + h] = fr.x + fr.y;
    }
}

// attention scores -> e[p] = adj ? exp(score) : 0   (normalized in agg)
__device__ __forceinline__ void gat_scores(SubS& s, const float* __restrict__ attv,
                                           int tid, int adj0, int adj1)
{
#pragma unroll
    for (int rep = 0; rep < 2; ++rep) {
        const int p = tid + rep * TPG;
        if (p >= NN * NN) break;
        const int adjv = rep == 0 ? adj0 : adj1;
        const int i = p / NN, j = p - (p / NN) * NN;
        float ev = 0.0f;
        if (adjv) {
            float a0 = 0.f, a1 = 0.f;
            const float4* xlj = (const float4*)(s.xl + j * PAD);
            const float4* xri = (const float4*)(s.xr + i * PAD);
            const float4* at4 = (const float4*)attv;
#pragma unroll
            for (int k = 0; k < 16; k += 2) {
                float4 l0 = xlj[k],     r0 = xri[k],     w0 = at4[k];
                float4 l1 = xlj[k + 1], r1 = xri[k + 1], w1 = at4[k + 1];
                a0 = fmaf(lrelu(l0.x + r0.x), w0.x, a0);
                a0 = fmaf(lrelu(l0.y + r0.y), w0.y, a0);
                a0 = fmaf(lrelu(l0.z + r0.z), w0.z, a0);
                a0 = fmaf(lrelu(l0.w + r0.w), w0.w, a0);
                a1 = fmaf(lrelu(l1.x + r1.x), w1.x, a1);
                a1 = fmaf(lrelu(l1.y + r1.y), w1.y, a1);
                a1 = fmaf(lrelu(l1.z + r1.z), w1.z, a1);
                a1 = fmaf(lrelu(l1.w + r1.w), w1.w, a1);
            }
            ev = __expf(a0 + a1);
        }
        s.e[p] = ev;
    }
}

// out[n,h] = relu( (sum_j e[n,j]*xl[j,h]) / rowsum + bias [+ alpha*skip] ), 6 rows/thread
__device__ __forceinline__ void gat_agg6(SubS& s, const float* __restrict__ bias,
                                         float* __restrict__ xout, int h, int gg,
                                         const float* skipreg, int mode)
{
    const int nb = gg * 6;
    float xv[NN];
#pragma unroll
    for (int j = 0; j < NN; ++j) xv[j] = s.xl[j * PAD + h];
    const float bv = bias[h];
#pragma unroll
    for (int r = 0; r < 6; ++r) {
        const float4* e4 = (const float4*)(s.e + (nb + r) * NN);
        float4 e0 = e4[0], e1 = e4[1], e2 = e4[2];
        float rs = ((e0.x + e0.y) + (e0.z + e0.w))
                 + ((e1.x + e1.y) + (e1.z + e1.w))
                 + ((e2.x + e2.y) + (e2.z + e2.w));
        float a = 0.f;
        a = fmaf(e0.x, xv[0], a);  a = fmaf(e0.y, xv[1], a);
        a = fmaf(e0.z, xv[2], a);  a = fmaf(e0.w, xv[3], a);
        a = fmaf(e1.x, xv[4], a);  a = fmaf(e1.y, xv[5], a);
        a = fmaf(e1.z, xv[6], a);  a = fmaf(e1.w, xv[7], a);
        a = fmaf(e2.x, xv[8], a);  a = fmaf(e2.y, xv[9], a);
        a = fmaf(e2.z, xv[10], a); a = fmaf(e2.w, xv[11], a);
        a = fmaf(a, __frcp_rn(rs), bv);
        if (mode == 1) a += ALPHA * skipreg[r];
        xout[(nb + r) * HID + h] = fmaxf(a, 0.f);
    }
}

// Gabriel adjacency for pair p (symmetric); latent in smem
__device__ __forceinline__ int gabriel_adj(const SubS& s, int p)
{
    const int i = p / NN, j = p - (p / NN) * NN;
    if (i == j) return 1;
    float xi = s.latent[i * 4], yi = s.latent[i * 4 + 1];
    float xj = s.latent[j * 4], yj = s.latent[j * 4 + 1];
    float dx = xi - xj, dy = yi - yj;
    float r2 = (dx * dx + dy * dy) * 0.25f;
    float mx = (xi + xj) * 0.5f, my = (yi + yj) * 0.5f;
    int ok = 1;
#pragma unroll
    for (int k = 0; k < NN; ++k) {
        if (k == i || k == j) continue;
        float ax = s.latent[k * 4] - mx;
        float ay = s.latent[k * 4 + 1] - my;
        float d2 = ax * ax + ay * ay;
        ok &= (d2 > r2) ? 1 : 0;
    }
    return ok;
}

__global__ void __launch_bounds__(NTH, 1)
gae_kernel(const float* __restrict__ batch,
           const float* __restrict__ enc_w1, const float* __restrict__ enc_b1,
           const float* __restrict__ enc_w2, const float* __restrict__ enc_b2,
           const float* __restrict__ enc_w3, const float* __restrict__ enc_b3,
           const float* __restrict__ g1_wl, const float* __restrict__ g1_wr,
           const float* __restrict__ g1_att, const float* __restrict__ g1_b,
           const float* __restrict__ g2_wl, const float* __restrict__ g2_wr,
           const float* __restrict__ g2_att, const float* __restrict__ g2_b,
           const float* __restrict__ g3_wl, const float* __restrict__ g3_wr,
           const float* __restrict__ g3_att, const float* __restrict__ g3_b,
           const float* __restrict__ g4_wl, const float* __restrict__ g4_wr,
           const float* __restrict__ g4_att, const float* __restrict__ g4_b,
           const float* __restrict__ lab_w, const float* __restrict__ lab_b,
           const float* __restrict__ val_w, const float* __restrict__ val_b,
           const float* __restrict__ skip_w, const float* __restrict__ skip_b,
           float* __restrict__ out)
{
    extern __shared__ unsigned char smraw[];
    SM& S = *reinterpret_cast<SM*>(smraw);
    const int T = threadIdx.x;

    // ---- stage weights (strided loops) ----
    for (int i = T; i < HID * HID; i += NTH) {
        const int k = i >> 6, hh = i & 63;
        const int d = hh * PAD + k;
        S.w_enc2t[d] = enc_w2[i];
        S.wl2t[d] = g2_wl[i]; S.wr2t[d] = g2_wr[i];
        S.wl3t[d] = g3_wl[i]; S.wr3t[d] = g3_wr[i];
        S.wl4t[d] = g4_wl[i]; S.wr4t[d] = g4_wr[i];
    }
    for (int i = T; i < 5 * HID; i += NTH) S.w_enc1[i] = enc_w1[i];
    for (int i = T; i < 4 * HID; i += NTH) S.w_lab[i] = lab_w[i];
    for (int i = T; i < 3 * HID; i += NTH) { S.w_enc3[i] = enc_w3[i]; S.w_skip[i] = skip_w[i]; }
    if (T < HID) {
        const int i = T;
        S.b_enc1[i] = enc_b1[i]; S.b_enc2[i] = enc_b2[i];
        S.g_wl1[i] = g1_wl[i];   S.g_wr1[i] = g1_wr[i];
        S.att1[i] = g1_att[i];   S.gb1[i] = g1_b[i];
        S.att2[i] = g2_att[i];   S.gb2[i] = g2_b[i];
        S.att3[i] = g3_att[i];   S.gb3[i] = g3_b[i];
        S.att4[i] = g4_att[i];   S.gb4[i] = g4_b[i];
        S.b_skip[i] = skip_b[i]; S.w_val[i] = val_w[i];
    } else if (T >= 64 && T < 67) {
        S.b_enc3[T - 64] = enc_b3[T - 64];
    } else if (T >= 68 && T < 72) {
        S.b_lab[T - 68] = lab_b[T - 68];
    } else if (T == 72) {
        S.b_val[0] = val_b[0];
    }
    __syncthreads();

    const int sb  = T / TPG;
    const int tid = T - sb * TPG;   // 0..127
    SubS& s = S.sub[sb];
    const int h  = tid & 63;
    const int gg = tid >> 6;        // 0 or 1
    const int nb = gg * 6;
    const int b = blockIdx.x * NSUB + sb;
    const bool active = (b < NB);

    // ---- input + passthrough ----
    if (active && tid < 60) {
        float v = batch[(size_t)b * 60 + tid];
        s.binp[tid] = v;
        int n = tid / 5, c = tid - n * 5;
        if (c < 4) out[O1 + (size_t)b * 48 + n * 4 + c] = v;
        else       out[O2 + (size_t)b * 12 + n] = v;
    }
    barsub(sb);

    // ---- encoder layer 1 (K=5) -> xA ----
    {
        float a[6];
        const float bv = S.b_enc1[h];
#pragma unroll
        for (int r = 0; r < 6; ++r) a[r] = bv;
#pragma unroll
        for (int k = 0; k < 5; ++k) {
            float w = S.w_enc1[k * HID + h];
#pragma unroll
            for (int r = 0; r < 6; ++r)
                a[r] = fmaf(s.binp[(nb + r) * 5 + k], w, a[r]);
        }
#pragma unroll
        for (int r = 0; r < 6; ++r) s.xA[(nb + r) * HID + h] = fmaxf(a[r], 0.f);
    }
    barsub(sb);

    // ---- encoder layer 2 -> xC ----
    gemm64_relu6(s.xA, S.w_enc2t, S.b_enc2, s.xC, h, gg);
    barsub(sb);

    // ---- latent (64->3) + emit ----
    if (tid < 36) {
        int n = tid / 3, c = tid - n * 3;
        float a = S.b_enc3[c];
#pragma unroll
        for (int k = 0; k < 64; k += 2) {
            int k0 = (k + tid) & 63, k1 = (k + 1 + tid) & 63;
            a = fmaf(s.xC[n * HID + k0], S.w_enc3[k0 * 3 + c], a);
            a = fmaf(s.xC[n * HID + k1], S.w_enc3[k1 * 3 + c], a);
        }
        s.latent[n * 4 + c] = a;
        if (active) out[OT + (size_t)b * 36 + n * 3 + c] = a;
    }
    barsub(sb);

    // ---- adjacency (registers) + skip (registers) + GAT1 projections ----
    const int adj0 = gabriel_adj(s, tid);
    const int adj1 = (tid < NN * NN - TPG) ? gabriel_adj(s, tid + TPG) : 0;
    float skipreg[6];
    {
        const float bv = S.b_skip[h];
#pragma unroll
        for (int r = 0; r < 6; ++r) skipreg[r] = bv;
#pragma unroll
        for (int c = 0; c < 3; ++c) {
            float w = S.w_skip[c * HID + h];
#pragma unroll
            for (int r = 0; r < 6; ++r)
                skipreg[r] = fmaf(s.latent[(nb + r) * 4 + c], w, skipreg[r]);
        }
    }
    {
        float wl = S.g_wl1[h], wr = S.g_wr1[h];
#pragma unroll
        for (int r = 0; r < 6; ++r) {
            float v = s.latent[(nb + r) * 4 + 2];
            s.xl[(nb + r) * PAD + h] = v * wl;
            s.xr[(nb + r) * PAD + h] = v * wr;
        }
    }
    barsub(sb);

    // ---- GAT 1 -> xA (x1) ----
    gat_scores(s, S.att1, tid, adj0, adj1);
    barsub(sb);
    gat_agg6(s, S.gb1, s.xA, h, gg, skipreg, 0);
    barsub(sb);

    // ---- GAT 2 -> xC (x2) ----
    dual_gemm6(s.xA, S.wl2t, S.wr2t, s.xl, s.xr, h, gg);
    barsub(sb);
    gat_scores(s, S.att2, tid, adj0, adj1);
    barsub(sb);
    gat_agg6(s, S.gb2, s.xC, h, gg, skipreg, 0);
    barsub(sb);

    // ---- GAT 3 -> xA (x3) ----
    dual_gemm6(s.xC, S.wl3t, S.wr3t, s.xl, s.xr, h, gg);
    barsub(sb);
    gat_scores(s, S.att3, tid, adj0, adj1);
    barsub(sb);
    gat_agg6(s, S.gb3, s.xA, h, gg, skipreg, 1);
    barsub(sb);

    // ---- GAT 4 projections (reads xC = x2) + logits head (reads xA = x3) ----
    dual_gemm6(s.xC, S.wl4t, S.wr4t, s.xl, s.xr, h, gg);
    if (active && tid < 48) {
        int n = tid / 4, c = tid - n * 4;
        float a = S.b_lab[c];
#pragma unroll
        for (int k = 0; k < 64; k += 2) {
            int k0 = (k + tid) & 63, k1 = (k + 1 + tid) & 63;
            a = fmaf(s.xA[n * HID + k0], S.w_lab[k0 * 4 + c], a);
            a = fmaf(s.xA[n * HID + k1], S.w_lab[k1 * 4 + c], a);
        }
        out[OL + (size_t)b * 48 + n * 4 + c] = a;
    }
    barsub(sb);

    // ---- GAT 4 -> xA (x4) ----
    gat_scores(s, S.att4, tid, adj0, adj1);
    barsub(sb);
    gat_agg6(s, S.gb4, s.xA, h, gg, skipreg, 1);
    barsub(sb);

    // ---- values head ----
    if (active && tid < NN) {
        float a = S.b_val[0];
#pragma unroll
        for (int k = 0; k < 64; k += 2) {
            int k0 = (k + tid) & 63, k1 = (k + 1 + tid) & 63;
            a = fmaf(s.xA[tid * HID + k0], S.w_val[k0], a);
            a = fmaf(s.xA[tid * HID + k1], S.w_val[k1], a);
        }
        out[OV + (size_t)b * 12 + tid] = a;
    }
}

} // anonymous namespace

extern "C" void kernel_launch(void* const* d_in, const int* in_sizes, int n_in,
                              void* d_out, int out_size)
{
    const float* p[29];
    for (int i = 0; i < 29; ++i) p[i] = (const float*)d_in[i];
    float* out = (float*)d_out;

    cudaFuncSetAttribute(gae_kernel, cudaFuncAttributeMaxDynamicSharedMemorySize,
                         (int)sizeof(SM));

    gae_kernel<<<GRID, NTH, sizeof(SM)>>>(
        p[0],
        p[1], p[2], p[3], p[4], p[5], p[6],
        p[7], p[8], p[9], p[10],
        p[11], p[12], p[13], p[14],
        p[15], p[16], p[17], p[18],
        p[19], p[20], p[21], p[22],
        p[23], p[24], p[25], p[26], p[27], p[28],
        out);
}